// round 2
// baseline (speedup 1.0000x reference)
#include <cuda_runtime.h>
#include <math.h>
#include <float.h>

#define BATCH 4096
#define NLAT  256
#define NCHAR 128
#define NH    1024
#define NH3   3072
#define NSTEP 64
#define LDW   1280   // H + L, row stride of w_ih0 / h2o_w

// ---------------- scratch (device globals; no allocation allowed) ----------
__device__ float g_Z0[BATCH * NH3];     // z @ w_ih0[:,H:]^T + b_ih0
__device__ float g_T0[NCHAR * NH3];     // swish(embed) @ w_ih0[:,:H]^T
__device__ float g_Esw[NCHAR * NH];     // swish(embed_w)
__device__ float g_OutZ[BATCH * NCHAR]; // z @ h2o_w[:,H:]^T + h2o_b
__device__ float g_h1[BATCH * NH];
__device__ float g_h2[BATCH * NH];
__device__ float g_bufA[BATCH * NH3];
__device__ float g_bufB[BATCH * NH3];
__device__ int   g_c[BATCH];

// ---------------- small kernels --------------------------------------------
__global__ void init_c_kernel(int* __restrict__ c) {
    int i = blockIdx.x * blockDim.x + threadIdx.x;
    if (i < BATCH) c[i] = 0;  // SOS
}

__global__ void swish_kernel(const float* __restrict__ e, float* __restrict__ o, int n) {
    int i = blockIdx.x * blockDim.x + threadIdx.x;
    if (i < n) {
        float v = e[i];
        o[i] = v / (1.0f + expf(-v));
    }
}

// GRU gate fusion. gi may be augmented by a gathered table row T0[c[b]].
// h updated in place: h' = (1-z)*n + z*h  (PyTorch GRUCell math)
__global__ void gru_gates_kernel(const float* __restrict__ gi,
                                 const float* __restrict__ T0,
                                 const int*   __restrict__ c,
                                 const float* __restrict__ gh,
                                 float*       __restrict__ h)
{
    int idx = blockIdx.x * blockDim.x + threadIdx.x;   // over BATCH*NH
    int b = idx >> 10;          // / NH
    int i = idx & (NH - 1);
    size_t base = (size_t)b * NH3;
    float gir = gi[base + i];
    float giz = gi[base + NH + i];
    float gin = gi[base + 2 * NH + i];
    if (T0) {
        size_t tb = (size_t)c[b] * NH3;
        gir += T0[tb + i];
        giz += T0[tb + NH + i];
        gin += T0[tb + 2 * NH + i];
    }
    float ghr = gh[base + i];
    float ghz = gh[base + NH + i];
    float ghn = gh[base + 2 * NH + i];
    float r  = 1.0f / (1.0f + expf(-(gir + ghr)));
    float zg = 1.0f / (1.0f + expf(-(giz + ghz)));
    float nn = tanhf(gin + r * ghn);
    float hv = h[idx];
    h[idx] = (1.0f - zg) * nn + zg * hv;
}

// ---------------- generic SGEMM: C = A * B^T (+bias) -----------------------
// A: [M,K] row-major lda, B: [N,K] row-major ldb, C: [M,N] ldc.
// BM=BN=128, BK=16, 256 threads, 8x8 per thread, reg prefetch.
// Requires M%128==0, N%128==0, K%16==0, lda/ldb/ldc %4==0, 16B-aligned bases.
__global__ __launch_bounds__(256, 2)
void sgemm128(int K,
              const float* __restrict__ A, int lda,
              const float* __restrict__ B, int ldb,
              const float* __restrict__ bias,
              float* __restrict__ Cm, int ldc)
{
    __shared__ float As[16 * 132];
    __shared__ float Bs[16 * 132];
    const int tid = threadIdx.x;
    const int bn = blockIdx.x * 128;
    const int bm = blockIdx.y * 128;

    const int lr = tid >> 2;          // 0..63 (row within 64-row half)
    const int lk = (tid & 3) << 2;    // k offset 0,4,8,12

    const float* Ap = A + (size_t)(bm + lr) * lda + lk;
    const float* Bp = B + (size_t)(bn + lr) * ldb + lk;

    const int tx = tid & 15;          // 16 col groups of 8
    const int ty = tid >> 4;          // 16 row groups of 8

    float acc[8][8];
#pragma unroll
    for (int i = 0; i < 8; i++)
#pragma unroll
        for (int j = 0; j < 8; j++) acc[i][j] = 0.0f;

    float4 pa0 = *(const float4*)Ap;
    float4 pa1 = *(const float4*)(Ap + (size_t)64 * lda);
    float4 pb0 = *(const float4*)Bp;
    float4 pb1 = *(const float4*)(Bp + (size_t)64 * ldb);

    const int ntiles = K >> 4;
    for (int tk = 0; tk < ntiles; ++tk) {
        As[(lk + 0) * 132 + lr] = pa0.x;
        As[(lk + 1) * 132 + lr] = pa0.y;
        As[(lk + 2) * 132 + lr] = pa0.z;
        As[(lk + 3) * 132 + lr] = pa0.w;
        As[(lk + 0) * 132 + lr + 64] = pa1.x;
        As[(lk + 1) * 132 + lr + 64] = pa1.y;
        As[(lk + 2) * 132 + lr + 64] = pa1.z;
        As[(lk + 3) * 132 + lr + 64] = pa1.w;
        Bs[(lk + 0) * 132 + lr] = pb0.x;
        Bs[(lk + 1) * 132 + lr] = pb0.y;
        Bs[(lk + 2) * 132 + lr] = pb0.z;
        Bs[(lk + 3) * 132 + lr] = pb0.w;
        Bs[(lk + 0) * 132 + lr + 64] = pb1.x;
        Bs[(lk + 1) * 132 + lr + 64] = pb1.y;
        Bs[(lk + 2) * 132 + lr + 64] = pb1.z;
        Bs[(lk + 3) * 132 + lr + 64] = pb1.w;
        __syncthreads();

        if (tk + 1 < ntiles) {
            const float* An = Ap + (tk + 1) * 16;
            const float* Bn = Bp + (tk + 1) * 16;
            pa0 = *(const float4*)An;
            pa1 = *(const float4*)(An + (size_t)64 * lda);
            pb0 = *(const float4*)Bn;
            pb1 = *(const float4*)(Bn + (size_t)64 * ldb);
        }

#pragma unroll
        for (int k = 0; k < 16; ++k) {
            float4 a0 = *(const float4*)&As[k * 132 + ty * 8];
            float4 a1 = *(const float4*)&As[k * 132 + ty * 8 + 4];
            float4 b0 = *(const float4*)&Bs[k * 132 + tx * 8];
            float4 b1 = *(const float4*)&Bs[k * 132 + tx * 8 + 4];
            float av[8] = {a0.x, a0.y, a0.z, a0.w, a1.x, a1.y, a1.z, a1.w};
            float bv[8] = {b0.x, b0.y, b0.z, b0.w, b1.x, b1.y, b1.z, b1.w};
#pragma unroll
            for (int i = 0; i < 8; i++)
#pragma unroll
                for (int j = 0; j < 8; j++)
                    acc[i][j] += av[i] * bv[j];
        }
        __syncthreads();
    }

    float bb[8];
#pragma unroll
    for (int j = 0; j < 8; j++) bb[j] = bias ? bias[bn + tx * 8 + j] : 0.0f;

#pragma unroll
    for (int i = 0; i < 8; i++) {
        float* Cp = Cm + (size_t)(bm + ty * 8 + i) * ldc + bn + tx * 8;
        float4 v0 = make_float4(acc[i][0] + bb[0], acc[i][1] + bb[1],
                                acc[i][2] + bb[2], acc[i][3] + bb[3]);
        float4 v1 = make_float4(acc[i][4] + bb[4], acc[i][5] + bb[5],
                                acc[i][6] + bb[6], acc[i][7] + bb[7]);
        *(float4*)Cp = v0;
        *(float4*)(Cp + 4) = v1;
    }
}

// ---------------- fused output GEMM + argmax -------------------------------
// logits[b, :] = h2[b] @ h2o_w[:, :H]^T + OutZ[b];  write to out[b, t, :],
// argmax -> cbuf. Block: 32 rows x 128 cols, BK=32, K=1024, 256 threads.
__global__ __launch_bounds__(256, 2)
void h2o_argmax_kernel(const float* __restrict__ h2,
                       const float* __restrict__ W,     // h2o_w, ldb=1280
                       const float* __restrict__ OutZ,
                       float* __restrict__ out, int t,
                       int* __restrict__ cbuf)
{
    __shared__ float As[32 * 36];
    __shared__ float Bs[32 * 132];   // reused as logits buffer afterwards
    const int tid = threadIdx.x;
    const int bm = blockIdx.x * 32;
    const int ar = tid >> 3;          // 0..31
    const int ak = (tid & 7) << 2;    // 0..28
    const int tx = tid & 15;
    const int ty = tid >> 4;          // 0..15 -> 2 rows each
    float acc[2][8];
#pragma unroll
    for (int i = 0; i < 2; i++)
#pragma unroll
        for (int j = 0; j < 8; j++) acc[i][j] = 0.0f;

    for (int kt = 0; kt < NH; kt += 32) {
        float4 av = *(const float4*)(h2 + (size_t)(bm + ar) * NH + kt + ak);
        As[(ak + 0) * 36 + ar] = av.x;
        As[(ak + 1) * 36 + ar] = av.y;
        As[(ak + 2) * 36 + ar] = av.z;
        As[(ak + 3) * 36 + ar] = av.w;
#pragma unroll
        for (int p = 0; p < 4; ++p) {
            float4 bv = *(const float4*)(W + (size_t)(ar + p * 32) * LDW + kt + ak);
            Bs[(ak + 0) * 132 + ar + p * 32] = bv.x;
            Bs[(ak + 1) * 132 + ar + p * 32] = bv.y;
            Bs[(ak + 2) * 132 + ar + p * 32] = bv.z;
            Bs[(ak + 3) * 132 + ar + p * 32] = bv.w;
        }
        __syncthreads();
#pragma unroll
        for (int k = 0; k < 32; ++k) {
            float a0 = As[k * 36 + ty * 2];
            float a1 = As[k * 36 + ty * 2 + 1];
            float4 b0 = *(const float4*)&Bs[k * 132 + tx * 8];
            float4 b1 = *(const float4*)&Bs[k * 132 + tx * 8 + 4];
            acc[0][0] += a0 * b0.x; acc[0][1] += a0 * b0.y;
            acc[0][2] += a0 * b0.z; acc[0][3] += a0 * b0.w;
            acc[0][4] += a0 * b1.x; acc[0][5] += a0 * b1.y;
            acc[0][6] += a0 * b1.z; acc[0][7] += a0 * b1.w;
            acc[1][0] += a1 * b0.x; acc[1][1] += a1 * b0.y;
            acc[1][2] += a1 * b0.z; acc[1][3] += a1 * b0.w;
            acc[1][4] += a1 * b1.x; acc[1][5] += a1 * b1.y;
            acc[1][6] += a1 * b1.z; acc[1][7] += a1 * b1.w;
        }
        __syncthreads();
    }

    // epilogue: add OutZ, write out[b, t, :], stash logits in Bs
#pragma unroll
    for (int i = 0; i < 2; i++) {
        int row = ty * 2 + i;
        const float* ozp = OutZ + (size_t)(bm + row) * NCHAR + tx * 8;
        float v[8];
#pragma unroll
        for (int j = 0; j < 8; j++) v[j] = acc[i][j] + ozp[j];
#pragma unroll
        for (int j = 0; j < 8; j++) Bs[row * 132 + tx * 8 + j] = v[j];
        float* op = out + (size_t)(bm + row) * (NSTEP * NCHAR) + t * NCHAR + tx * 8;
        *(float4*)op = make_float4(v[0], v[1], v[2], v[3]);
        *(float4*)(op + 4) = make_float4(v[4], v[5], v[6], v[7]);
    }
    __syncthreads();
    if (tid < 32) {
        float best = -FLT_MAX;
        int bi = 0;
        for (int n = 0; n < 128; ++n) {
            float v = Bs[tid * 132 + n];
            if (v > best) { best = v; bi = n; }   // first-max tiebreak == jnp.argmax
        }
        cbuf[bm + tid] = bi;
    }
}

// ---------------- launch ----------------------------------------------------
extern "C" void kernel_launch(void* const* d_in, const int* in_sizes, int n_in,
                              void* d_out, int out_size)
{
    const float* z       = (const float*)d_in[0];
    const float* embed_w = (const float*)d_in[1];
    const float* z2h_w   = (const float*)d_in[2];
    const float* z2h_b   = (const float*)d_in[3];
    const float* w_ih0   = (const float*)d_in[4];
    const float* w_hh0   = (const float*)d_in[5];
    const float* b_ih0   = (const float*)d_in[6];
    const float* b_hh0   = (const float*)d_in[7];
    const float* w_ih1   = (const float*)d_in[8];
    const float* w_hh1   = (const float*)d_in[9];
    const float* b_ih1   = (const float*)d_in[10];
    const float* b_hh1   = (const float*)d_in[11];
    const float* h2o_w   = (const float*)d_in[12];
    const float* h2o_b   = (const float*)d_in[13];
    float* out = (float*)d_out;

    float *Z0, *T0, *Esw, *OutZ, *h1, *h2, *bufA, *bufB;
    int* cbuf;
    cudaGetSymbolAddress((void**)&Z0,   g_Z0);
    cudaGetSymbolAddress((void**)&T0,   g_T0);
    cudaGetSymbolAddress((void**)&Esw,  g_Esw);
    cudaGetSymbolAddress((void**)&OutZ, g_OutZ);
    cudaGetSymbolAddress((void**)&h1,   g_h1);
    cudaGetSymbolAddress((void**)&h2,   g_h2);
    cudaGetSymbolAddress((void**)&bufA, g_bufA);
    cudaGetSymbolAddress((void**)&bufB, g_bufB);
    cudaGetSymbolAddress((void**)&cbuf, g_c);

    // ---- per-replay precompute ----
    init_c_kernel<<<(BATCH + 255) / 256, 256>>>(cbuf);
    swish_kernel<<<(NCHAR * NH + 255) / 256, 256>>>(embed_w, Esw, NCHAR * NH);
    // T0 = Esw @ w_ih0[:, :H]^T          [128, 3072]
    sgemm128<<<dim3(NH3 / 128, NCHAR / 128), 256>>>(NH, Esw, NH, w_ih0, LDW, nullptr, T0, NH3);
    // Z0 = z @ w_ih0[:, H:]^T + b_ih0    [4096, 3072]
    sgemm128<<<dim3(NH3 / 128, BATCH / 128), 256>>>(NLAT, z, NLAT, w_ih0 + NH, LDW, b_ih0, Z0, NH3);
    // OutZ = z @ h2o_w[:, H:]^T + h2o_b  [4096, 128]
    sgemm128<<<dim3(NCHAR / 128, BATCH / 128), 256>>>(NLAT, z, NLAT, h2o_w + NH, LDW, h2o_b, OutZ, NCHAR);
    // h1 = h2 = z @ z2h_w^T + z2h_b      [4096, 1024]
    sgemm128<<<dim3(NH / 128, BATCH / 128), 256>>>(NLAT, z, NLAT, z2h_w, NLAT, z2h_b, h1, NH);
    sgemm128<<<dim3(NH / 128, BATCH / 128), 256>>>(NLAT, z, NLAT, z2h_w, NLAT, z2h_b, h2, NH);

    // ---- 64 recurrent steps ----
    for (int t = 0; t < NSTEP; ++t) {
        // gh0 = h1 @ w_hh0^T + b_hh0
        sgemm128<<<dim3(NH3 / 128, BATCH / 128), 256>>>(NH, h1, NH, w_hh0, NH, b_hh0, bufA, NH3);
        // h1 <- gru( Z0 + T0[c], gh0, h1 )
        gru_gates_kernel<<<BATCH * NH / 256, 256>>>(Z0, T0, cbuf, bufA, h1);
        // gi1 = h1 @ w_ih1^T + b_ih1
        sgemm128<<<dim3(NH3 / 128, BATCH / 128), 256>>>(NH, h1, NH, w_ih1, NH, b_ih1, bufA, NH3);
        // gh1 = h2 @ w_hh1^T + b_hh1
        sgemm128<<<dim3(NH3 / 128, BATCH / 128), 256>>>(NH, h2, NH, w_hh1, NH, b_hh1, bufB, NH3);
        // h2 <- gru( gi1, gh1, h2 )
        gru_gates_kernel<<<BATCH * NH / 256, 256>>>(bufA, nullptr, nullptr, bufB, h2);
        // logits -> out[:, t, :], argmax -> c
        h2o_argmax_kernel<<<BATCH / 32, 256>>>(h2, h2o_w, OutZ, out, t, cbuf);
    }
}

// round 5
// speedup vs baseline: 2.9782x; 2.9782x over previous
#include <cuda_runtime.h>
#include <cuda_bf16.h>
#include <math.h>
#include <float.h>
#include <stdint.h>

#define BATCH 4096
#define NLAT  256
#define NCHAR 128
#define NH    1024
#define NH3   3072
#define NSTEP 64
#define LDW   1280   // H + L, row stride of w_ih0 / h2o_w
#define KCH   48     // virtual K chunks of 64 (3 x 1024/64)

// ===================== scratch (device globals) =============================
__device__ float g_Z0[BATCH * NH3];
__device__ float g_T0[NCHAR * NH3];
__device__ float g_Esw[NCHAR * NH];
__device__ float g_OutZ[BATCH * NCHAR];
__device__ float g_h1[BATCH * NH];
__device__ float g_h2[BATCH * NH];
__device__ float g_bufA[BATCH * NH3];
__device__ float g_bufB[BATCH * NH3];
__device__ int   g_c[BATCH];
// bf16 hi/lo splits (16B-aligned for cp.async)
__device__ __align__(16) __nv_bfloat16 g_h1hi[BATCH * NH], g_h1lo[BATCH * NH];
__device__ __align__(16) __nv_bfloat16 g_h2hi[BATCH * NH], g_h2lo[BATCH * NH];
__device__ __align__(16) __nv_bfloat16 g_Whh0hi[NH3 * NH], g_Whh0lo[NH3 * NH];
__device__ __align__(16) __nv_bfloat16 g_Wih1hi[NH3 * NH], g_Wih1lo[NH3 * NH];
__device__ __align__(16) __nv_bfloat16 g_Whh1hi[NH3 * NH], g_Whh1lo[NH3 * NH];
__device__ __align__(16) __nv_bfloat16 g_Wouthi[NCHAR * NH], g_Woutlo[NCHAR * NH];

// ===================== small kernels ========================================
__global__ void init_c_kernel(int* __restrict__ c) {
    int i = blockIdx.x * blockDim.x + threadIdx.x;
    if (i < BATCH) c[i] = 0;
}
__global__ void swish_kernel(const float* __restrict__ e, float* __restrict__ o, int n) {
    int i = blockIdx.x * blockDim.x + threadIdx.x;
    if (i < n) { float v = e[i]; o[i] = v / (1.0f + expf(-v)); }
}
__global__ void split_kernel(const float* __restrict__ src, int stride,
                             __nv_bfloat16* __restrict__ hi,
                             __nv_bfloat16* __restrict__ lo, int total) {
    int i = blockIdx.x * blockDim.x + threadIdx.x;
    if (i < total) {
        int r = i >> 10, cc = i & 1023;
        float v = src[(size_t)r * stride + cc];
        __nv_bfloat16 h = __float2bfloat16(v);
        hi[i] = h;
        lo[i] = __float2bfloat16(v - __bfloat162float(h));
    }
}

__global__ void gru_gates_kernel(const float* __restrict__ gi,
                                 const float* __restrict__ T0,
                                 const int*   __restrict__ c,
                                 const float* __restrict__ gh,
                                 float*       __restrict__ h,
                                 __nv_bfloat16* __restrict__ hhi,
                                 __nv_bfloat16* __restrict__ hlo)
{
    int idx = blockIdx.x * blockDim.x + threadIdx.x;
    int b = idx >> 10;
    int i = idx & (NH - 1);
    size_t base = (size_t)b * NH3;
    float gir = gi[base + i];
    float giz = gi[base + NH + i];
    float gin = gi[base + 2 * NH + i];
    if (T0) {
        size_t tb = (size_t)c[b] * NH3;
        gir += T0[tb + i];
        giz += T0[tb + NH + i];
        gin += T0[tb + 2 * NH + i];
    }
    float ghr = gh[base + i];
    float ghz = gh[base + NH + i];
    float ghn = gh[base + 2 * NH + i];
    float r  = 1.0f / (1.0f + expf(-(gir + ghr)));
    float zg = 1.0f / (1.0f + expf(-(giz + ghz)));
    float nn = tanhf(gin + r * ghn);
    float hv = h[idx];
    float hn = (1.0f - zg) * nn + zg * hv;
    h[idx] = hn;
    __nv_bfloat16 hb = __float2bfloat16(hn);
    hhi[idx] = hb;
    hlo[idx] = __float2bfloat16(hn - __bfloat162float(hb));
}

// ===================== SIMT sgemm for per-launch precompute =================
__global__ __launch_bounds__(256, 2)
void sgemm128(int K,
              const float* __restrict__ A, int lda,
              const float* __restrict__ B, int ldb,
              const float* __restrict__ bias,
              float* __restrict__ Cm, int ldc)
{
    __shared__ float As[16 * 132];
    __shared__ float Bs[16 * 132];
    const int tid = threadIdx.x;
    const int bn = blockIdx.x * 128;
    const int bm = blockIdx.y * 128;
    const int lr = tid >> 2;
    const int lk = (tid & 3) << 2;
    const float* Ap = A + (size_t)(bm + lr) * lda + lk;
    const float* Bp = B + (size_t)(bn + lr) * ldb + lk;
    const int tx = tid & 15;
    const int ty = tid >> 4;
    float acc[8][8];
#pragma unroll
    for (int i = 0; i < 8; i++)
#pragma unroll
        for (int j = 0; j < 8; j++) acc[i][j] = 0.0f;
    float4 pa0 = *(const float4*)Ap;
    float4 pa1 = *(const float4*)(Ap + (size_t)64 * lda);
    float4 pb0 = *(const float4*)Bp;
    float4 pb1 = *(const float4*)(Bp + (size_t)64 * ldb);
    const int ntiles = K >> 4;
    for (int tk = 0; tk < ntiles; ++tk) {
        As[(lk + 0) * 132 + lr] = pa0.x; As[(lk + 1) * 132 + lr] = pa0.y;
        As[(lk + 2) * 132 + lr] = pa0.z; As[(lk + 3) * 132 + lr] = pa0.w;
        As[(lk + 0) * 132 + lr + 64] = pa1.x; As[(lk + 1) * 132 + lr + 64] = pa1.y;
        As[(lk + 2) * 132 + lr + 64] = pa1.z; As[(lk + 3) * 132 + lr + 64] = pa1.w;
        Bs[(lk + 0) * 132 + lr] = pb0.x; Bs[(lk + 1) * 132 + lr] = pb0.y;
        Bs[(lk + 2) * 132 + lr] = pb0.z; Bs[(lk + 3) * 132 + lr] = pb0.w;
        Bs[(lk + 0) * 132 + lr + 64] = pb1.x; Bs[(lk + 1) * 132 + lr + 64] = pb1.y;
        Bs[(lk + 2) * 132 + lr + 64] = pb1.z; Bs[(lk + 3) * 132 + lr + 64] = pb1.w;
        __syncthreads();
        if (tk + 1 < ntiles) {
            const float* An = Ap + (tk + 1) * 16;
            const float* Bn = Bp + (tk + 1) * 16;
            pa0 = *(const float4*)An; pa1 = *(const float4*)(An + (size_t)64 * lda);
            pb0 = *(const float4*)Bn; pb1 = *(const float4*)(Bn + (size_t)64 * ldb);
        }
#pragma unroll
        for (int k = 0; k < 16; ++k) {
            float4 a0 = *(const float4*)&As[k * 132 + ty * 8];
            float4 a1 = *(const float4*)&As[k * 132 + ty * 8 + 4];
            float4 b0 = *(const float4*)&Bs[k * 132 + tx * 8];
            float4 b1 = *(const float4*)&Bs[k * 132 + tx * 8 + 4];
            float av[8] = {a0.x, a0.y, a0.z, a0.w, a1.x, a1.y, a1.z, a1.w};
            float bv[8] = {b0.x, b0.y, b0.z, b0.w, b1.x, b1.y, b1.z, b1.w};
#pragma unroll
            for (int i = 0; i < 8; i++)
#pragma unroll
                for (int j = 0; j < 8; j++)
                    acc[i][j] += av[i] * bv[j];
        }
        __syncthreads();
    }
    float bb[8];
#pragma unroll
    for (int j = 0; j < 8; j++) bb[j] = bias ? bias[bn + tx * 8 + j] : 0.0f;
#pragma unroll
    for (int i = 0; i < 8; i++) {
        float* Cp = Cm + (size_t)(bm + ty * 8 + i) * ldc + bn + tx * 8;
        *(float4*)Cp = make_float4(acc[i][0] + bb[0], acc[i][1] + bb[1],
                                   acc[i][2] + bb[2], acc[i][3] + bb[3]);
        *(float4*)(Cp + 4) = make_float4(acc[i][4] + bb[4], acc[i][5] + bb[5],
                                         acc[i][6] + bb[6], acc[i][7] + bb[7]);
    }
}

// ===================== mma.sync bf16 split GEMM =============================
// C[M,3072-or-128] = [Ah|Ah|Al] @ [Bh|Bl|Bh]^T over virtual K=3072.
// CTA 128x128, BK=64, 3-stage cp.async, 8 warps (2 M x 4 N), warp 64x32.
#define STAGE_BYTES 32768   // A 16KB + B 16KB
#define SMOFF(r, c) ((r) * 128 + ((((c) ^ ((r) & 7)) << 4)))

__device__ __forceinline__ uint32_t smem_u32(const void* p) {
    uint32_t a;
    asm("{ .reg .u64 t; cvta.to.shared.u64 t, %1; cvt.u32.u64 %0, t; }"
        : "=r"(a) : "l"(p));
    return a;
}
__device__ __forceinline__ void cp16(uint32_t dst, const void* src) {
    asm volatile("cp.async.cg.shared.global [%0], [%1], 16;"
                 :: "r"(dst), "l"(src));
}
__device__ __forceinline__ void ldm_x4(uint32_t* r, uint32_t addr) {
    asm volatile("ldmatrix.sync.aligned.m8n8.x4.shared.b16 {%0,%1,%2,%3}, [%4];"
                 : "=r"(r[0]), "=r"(r[1]), "=r"(r[2]), "=r"(r[3]) : "r"(addr));
}
__device__ __forceinline__ void mma16816(float* c, const uint32_t* a, const uint32_t* b) {
    asm volatile("mma.sync.aligned.m16n8k16.row.col.f32.bf16.bf16.f32 "
                 "{%0,%1,%2,%3}, {%4,%5,%6,%7}, {%8,%9}, {%0,%1,%2,%3};"
                 : "+f"(c[0]), "+f"(c[1]), "+f"(c[2]), "+f"(c[3])
                 : "r"(a[0]), "r"(a[1]), "r"(a[2]), "r"(a[3]), "r"(b[0]), "r"(b[1]));
}

__device__ __forceinline__ void issue_stage(
    uint32_t sm_stage, const __nv_bfloat16* Abase, const __nv_bfloat16* Bbase,
    int bm, int bn, int colH, int tid)
{
    int r = tid >> 1;
    int c0 = (tid & 1) * 4;
    const __nv_bfloat16* ag = Abase + (size_t)(bm + r) * NH + colH + c0 * 8;
    const __nv_bfloat16* bg = Bbase + (size_t)(bn + r) * NH + colH + c0 * 8;
    uint32_t sA = sm_stage;
    uint32_t sB = sm_stage + 16384;
#pragma unroll
    for (int j = 0; j < 4; ++j) {
        cp16(sA + SMOFF(r, c0 + j), ag + j * 8);
        cp16(sB + SMOFF(r, c0 + j), bg + j * 8);
    }
}

// mainloop producing acc[4][4][4] for this thread
__device__ __forceinline__ void mma_mainloop(
    const __nv_bfloat16* __restrict__ Ahi, const __nv_bfloat16* __restrict__ Alo,
    const __nv_bfloat16* __restrict__ Bhi, const __nv_bfloat16* __restrict__ Blo,
    int bm, int bn, char* smem, float acc[4][4][4])
{
    const int tid = threadIdx.x;
    const int wid = tid >> 5, l = tid & 31;
    const int wm = wid >> 2, wn = wid & 3;
    uint32_t sbase = smem_u32(smem);

#pragma unroll
    for (int mt = 0; mt < 4; ++mt)
#pragma unroll
        for (int nt = 0; nt < 4; ++nt)
#pragma unroll
            for (int e = 0; e < 4; ++e) acc[mt][nt][e] = 0.0f;

    // region selectors: kc<32 -> Ahi else Alo; 16<=kc<32 -> Blo else Bhi
    issue_stage(sbase, Ahi, Bhi, bm, bn, 0, tid);
    asm volatile("cp.async.commit_group;");
    issue_stage(sbase + STAGE_BYTES, Ahi, Bhi, bm, bn, 64, tid);
    asm volatile("cp.async.commit_group;");

#pragma unroll 1
    for (int kc = 0; kc < KCH; ++kc) {
        asm volatile("cp.async.wait_group 1;");
        __syncthreads();
        int kn = kc + 2;
        if (kn < KCH) {
            const __nv_bfloat16* Ab = (kn < 32) ? Ahi : Alo;
            const __nv_bfloat16* Bb = (kn >= 16 && kn < 32) ? Blo : Bhi;
            issue_stage(sbase + (kn % 3) * STAGE_BYTES, Ab, Bb, bm, bn,
                        (kn & 15) << 6, tid);
        }
        asm volatile("cp.async.commit_group;");

        uint32_t sA = sbase + (kc % 3) * STAGE_BYTES;
        uint32_t sB = sA + 16384;
#pragma unroll
        for (int kt = 0; kt < 4; ++kt) {
            uint32_t af[4][4];
#pragma unroll
            for (int mt = 0; mt < 4; ++mt) {
                int row = wm * 64 + mt * 16 + (l & 15);
                ldm_x4(af[mt], sA + SMOFF(row, kt * 2 + (l >> 4)));
            }
            uint32_t bf[4][2];
#pragma unroll
            for (int ntp = 0; ntp < 2; ++ntp) {
                int g = l >> 3;
                int nrow = wn * 32 + ntp * 16 + ((g >> 1) << 3) + (l & 7);
                uint32_t rr[4];
                ldm_x4(rr, sB + SMOFF(nrow, kt * 2 + (g & 1)));
                bf[2 * ntp][0] = rr[0]; bf[2 * ntp][1] = rr[1];
                bf[2 * ntp + 1][0] = rr[2]; bf[2 * ntp + 1][1] = rr[3];
            }
#pragma unroll
            for (int mt = 0; mt < 4; ++mt)
#pragma unroll
                for (int nt = 0; nt < 4; ++nt)
                    mma16816(acc[mt][nt], af[mt], bf[nt]);
        }
    }
    asm volatile("cp.async.wait_group 0;");
}

__global__ __launch_bounds__(256)
void gemm_big_mma(const __nv_bfloat16* __restrict__ Ahi, const __nv_bfloat16* __restrict__ Alo,
                  const __nv_bfloat16* __restrict__ Bhi, const __nv_bfloat16* __restrict__ Blo,
                  const float* __restrict__ bias, float* __restrict__ C)
{
    extern __shared__ char smem[];
    const int bn = blockIdx.x * 128, bm = blockIdx.y * 128;
    const int tid = threadIdx.x;
    const int wid = tid >> 5, l = tid & 31;
    const int wm = wid >> 2, wn = wid & 3;
    float acc[4][4][4];
    mma_mainloop(Ahi, Alo, Bhi, Blo, bm, bn, smem, acc);

#pragma unroll
    for (int mt = 0; mt < 4; ++mt) {
#pragma unroll
        for (int nt = 0; nt < 4; ++nt) {
            int row = bm + wm * 64 + mt * 16 + (l >> 2);
            int col = bn + wn * 32 + nt * 8 + ((l & 3) << 1);
            float b0 = bias[col], b1 = bias[col + 1];
            *(float2*)&C[(size_t)row * NH3 + col] =
                make_float2(acc[mt][nt][0] + b0, acc[mt][nt][1] + b1);
            *(float2*)&C[(size_t)(row + 8) * NH3 + col] =
                make_float2(acc[mt][nt][2] + b0, acc[mt][nt][3] + b1);
        }
    }
}

__global__ __launch_bounds__(256)
void h2o_mma_kernel(const __nv_bfloat16* __restrict__ Ahi, const __nv_bfloat16* __restrict__ Alo,
                    const __nv_bfloat16* __restrict__ Whi, const __nv_bfloat16* __restrict__ Wlo,
                    const float* __restrict__ OutZ,
                    float* __restrict__ out, int t, int* __restrict__ cbuf)
{
    extern __shared__ char smem[];
    const int bm = blockIdx.x * 128;
    const int tid = threadIdx.x;
    const int wid = tid >> 5, l = tid & 31;
    const int wm = wid >> 2, wn = wid & 3;
    float acc[4][4][4];
    mma_mainloop(Ahi, Alo, Whi, Wlo, bm, 0, smem, acc);
    __syncthreads();  // all warps done with stage smem before logits reuse

    float* lg = (float*)smem;   // [128][132]
#pragma unroll
    for (int mt = 0; mt < 4; ++mt)
#pragma unroll
        for (int nt = 0; nt < 4; ++nt) {
            int rl = wm * 64 + mt * 16 + (l >> 2);
            int cl = wn * 32 + nt * 8 + ((l & 3) << 1);
            lg[rl * 132 + cl]           = acc[mt][nt][0];
            lg[rl * 132 + cl + 1]       = acc[mt][nt][1];
            lg[(rl + 8) * 132 + cl]     = acc[mt][nt][2];
            lg[(rl + 8) * 132 + cl + 1] = acc[mt][nt][3];
        }
    __syncthreads();

    if (tid < 128) {
        int row = bm + tid;
        const float* oz = OutZ + (size_t)row * NCHAR;
        float* op = out + (size_t)row * (NSTEP * NCHAR) + t * NCHAR;
        float best = -FLT_MAX;
        int bi = 0;
#pragma unroll 4
        for (int c = 0; c < NCHAR; ++c) {
            float v = lg[tid * 132 + c] + oz[c];
            op[c] = v;
            if (v > best) { best = v; bi = c; }
        }
        cbuf[row] = bi;
    }
}

// ===================== launch ===============================================
extern "C" void kernel_launch(void* const* d_in, const int* in_sizes, int n_in,
                              void* d_out, int out_size)
{
    const float* z       = (const float*)d_in[0];
    const float* embed_w = (const float*)d_in[1];
    const float* z2h_w   = (const float*)d_in[2];
    const float* z2h_b   = (const float*)d_in[3];
    const float* w_ih0   = (const float*)d_in[4];
    const float* w_hh0   = (const float*)d_in[5];
    const float* b_ih0   = (const float*)d_in[6];
    const float* b_hh0   = (const float*)d_in[7];
    const float* w_ih1   = (const float*)d_in[8];
    const float* w_hh1   = (const float*)d_in[9];
    const float* b_ih1   = (const float*)d_in[10];
    const float* b_hh1   = (const float*)d_in[11];
    const float* h2o_w   = (const float*)d_in[12];
    const float* h2o_b   = (const float*)d_in[13];
    float* out = (float*)d_out;

    float *Z0, *T0, *Esw, *OutZ, *h1, *h2, *bufA, *bufB;
    int* cbuf;
    __nv_bfloat16 *h1hi, *h1lo, *h2hi, *h2lo;
    __nv_bfloat16 *Whh0hi, *Whh0lo, *Wih1hi, *Wih1lo, *Whh1hi, *Whh1lo, *Wouthi, *Woutlo;
    cudaGetSymbolAddress((void**)&Z0,   g_Z0);
    cudaGetSymbolAddress((void**)&T0,   g_T0);
    cudaGetSymbolAddress((void**)&Esw,  g_Esw);
    cudaGetSymbolAddress((void**)&OutZ, g_OutZ);
    cudaGetSymbolAddress((void**)&h1,   g_h1);
    cudaGetSymbolAddress((void**)&h2,   g_h2);
    cudaGetSymbolAddress((void**)&bufA, g_bufA);
    cudaGetSymbolAddress((void**)&bufB, g_bufB);
    cudaGetSymbolAddress((void**)&cbuf, g_c);
    cudaGetSymbolAddress((void**)&h1hi, g_h1hi);
    cudaGetSymbolAddress((void**)&h1lo, g_h1lo);
    cudaGetSymbolAddress((void**)&h2hi, g_h2hi);
    cudaGetSymbolAddress((void**)&h2lo, g_h2lo);
    cudaGetSymbolAddress((void**)&Whh0hi, g_Whh0hi);
    cudaGetSymbolAddress((void**)&Whh0lo, g_Whh0lo);
    cudaGetSymbolAddress((void**)&Wih1hi, g_Wih1hi);
    cudaGetSymbolAddress((void**)&Wih1lo, g_Wih1lo);
    cudaGetSymbolAddress((void**)&Whh1hi, g_Whh1hi);
    cudaGetSymbolAddress((void**)&Whh1lo, g_Whh1lo);
    cudaGetSymbolAddress((void**)&Wouthi, g_Wouthi);
    cudaGetSymbolAddress((void**)&Woutlo, g_Woutlo);

    const int smem_mma = 3 * STAGE_BYTES;  // 98304
    cudaFuncSetAttribute(gemm_big_mma, cudaFuncAttributeMaxDynamicSharedMemorySize, smem_mma);
    cudaFuncSetAttribute(h2o_mma_kernel, cudaFuncAttributeMaxDynamicSharedMemorySize, smem_mma);

    // ---- per-replay precompute ----
    init_c_kernel<<<(BATCH + 255) / 256, 256>>>(cbuf);
    swish_kernel<<<(NCHAR * NH + 255) / 256, 256>>>(embed_w, Esw, NCHAR * NH);
    sgemm128<<<dim3(NH3 / 128, 1), 256>>>(NH, Esw, NH, w_ih0, LDW, nullptr, T0, NH3);
    sgemm128<<<dim3(NH3 / 128, BATCH / 128), 256>>>(NLAT, z, NLAT, w_ih0 + NH, LDW, b_ih0, Z0, NH3);
    sgemm128<<<dim3(1, BATCH / 128), 256>>>(NLAT, z, NLAT, h2o_w + NH, LDW, h2o_b, OutZ, NCHAR);
    sgemm128<<<dim3(NH / 128, BATCH / 128), 256>>>(NLAT, z, NLAT, z2h_w, NLAT, z2h_b, h1, NH);
    sgemm128<<<dim3(NH / 128, BATCH / 128), 256>>>(NLAT, z, NLAT, z2h_w, NLAT, z2h_b, h2, NH);
    // splits
    split_kernel<<<BATCH * NH / 256, 256>>>(h1, NH, h1hi, h1lo, BATCH * NH);
    split_kernel<<<BATCH * NH / 256, 256>>>(h2, NH, h2hi, h2lo, BATCH * NH);
    split_kernel<<<NH3 * NH / 256, 256>>>(w_hh0, NH, Whh0hi, Whh0lo, NH3 * NH);
    split_kernel<<<NH3 * NH / 256, 256>>>(w_ih1, NH, Wih1hi, Wih1lo, NH3 * NH);
    split_kernel<<<NH3 * NH / 256, 256>>>(w_hh1, NH, Whh1hi, Whh1lo, NH3 * NH);
    split_kernel<<<NCHAR * NH / 256, 256>>>(h2o_w, LDW, Wouthi, Woutlo, NCHAR * NH);

    dim3 gbig(NH3 / 128, BATCH / 128);   // 24 x 32

    // ---- 64 recurrent steps ----
    for (int t = 0; t < NSTEP; ++t) {
        // gh0 = h1 @ w_hh0^T + b_hh0
        gemm_big_mma<<<gbig, 256, smem_mma>>>(h1hi, h1lo, Whh0hi, Whh0lo, b_hh0, bufA);
        // h1 <- gru(Z0 + T0[c], gh0, h1); emit h1 splits
        gru_gates_kernel<<<BATCH * NH / 256, 256>>>(Z0, T0, cbuf, bufA, h1, h1hi, h1lo);
        // gi1 = h1 @ w_ih1^T + b_ih1
        gemm_big_mma<<<gbig, 256, smem_mma>>>(h1hi, h1lo, Wih1hi, Wih1lo, b_ih1, bufA);
        // gh1 = h2 @ w_hh1^T + b_hh1
        gemm_big_mma<<<gbig, 256, smem_mma>>>(h2hi, h2lo, Whh1hi, Whh1lo, b_hh1, bufB);
        // h2 <- gru(gi1, gh1, h2); emit h2 splits
        gru_gates_kernel<<<BATCH * NH / 256, 256>>>(bufA, nullptr, nullptr, bufB, h2, h2hi, h2lo);
        // logits -> out[:, t, :], argmax -> c
        h2o_mma_kernel<<<BATCH / 128, 256, smem_mma>>>(h2hi, h2lo, Wouthi, Woutlo,
                                                       OutZ, out, t, cbuf);
    }
}

// round 6
// speedup vs baseline: 3.3440x; 1.1228x over previous
#include <cuda_runtime.h>
#include <cuda_bf16.h>
#include <math.h>
#include <float.h>
#include <stdint.h>

#define BATCH 4096
#define NLAT  256
#define NCHAR 128
#define NH    1024
#define NH3   3072
#define NSTEP 64
#define LDW   1280   // H + L, row stride of w_ih0 / h2o_w
#define KCH   48     // virtual K chunks of 64 (3 x 1024/64)

// ===================== scratch (device globals) =============================
__device__ float g_Z0[BATCH * NH3];
__device__ float g_T0[NCHAR * NH3];
__device__ float g_Esw[NCHAR * NH];
__device__ float g_OutZ[BATCH * NCHAR];
__device__ float g_h1[BATCH * NH];
__device__ float g_h2[BATCH * NH];
__device__ float g_bufA[BATCH * NH3];
__device__ float g_bufB[BATCH * NH3];
__device__ int   g_c[BATCH];
// bf16 hi/lo splits (16B-aligned for cp.async)
__device__ __align__(16) __nv_bfloat16 g_h1hi[BATCH * NH], g_h1lo[BATCH * NH];
__device__ __align__(16) __nv_bfloat16 g_h2hi[BATCH * NH], g_h2lo[BATCH * NH];
__device__ __align__(16) __nv_bfloat16 g_Whh0hi[NH3 * NH], g_Whh0lo[NH3 * NH];
__device__ __align__(16) __nv_bfloat16 g_Wih1hi[NH3 * NH], g_Wih1lo[NH3 * NH];
__device__ __align__(16) __nv_bfloat16 g_Whh1hi[NH3 * NH], g_Whh1lo[NH3 * NH];
__device__ __align__(16) __nv_bfloat16 g_Wouthi[NCHAR * NH], g_Woutlo[NCHAR * NH];

// ===================== small kernels ========================================
__global__ void init_c_kernel(int* __restrict__ c) {
    int i = blockIdx.x * blockDim.x + threadIdx.x;
    if (i < BATCH) c[i] = 0;
}
__global__ void swish_kernel(const float* __restrict__ e, float* __restrict__ o, int n) {
    int i = blockIdx.x * blockDim.x + threadIdx.x;
    if (i < n) { float v = e[i]; o[i] = v / (1.0f + expf(-v)); }
}
__global__ void split_kernel(const float* __restrict__ src, int stride,
                             __nv_bfloat16* __restrict__ hi,
                             __nv_bfloat16* __restrict__ lo, int total) {
    int i = blockIdx.x * blockDim.x + threadIdx.x;
    if (i < total) {
        int r = i >> 10, cc = i & 1023;
        float v = src[(size_t)r * stride + cc];
        __nv_bfloat16 h = __float2bfloat16(v);
        hi[i] = h;
        lo[i] = __float2bfloat16(v - __bfloat162float(h));
    }
}

__global__ void gru_gates_kernel(const float* __restrict__ gi,
                                 const float* __restrict__ T0,
                                 const int*   __restrict__ c,
                                 const float* __restrict__ gh,
                                 float*       __restrict__ h,
                                 __nv_bfloat16* __restrict__ hhi,
                                 __nv_bfloat16* __restrict__ hlo)
{
    int idx = blockIdx.x * blockDim.x + threadIdx.x;
    int b = idx >> 10;
    int i = idx & (NH - 1);
    size_t base = (size_t)b * NH3;
    float gir = gi[base + i];
    float giz = gi[base + NH + i];
    float gin = gi[base + 2 * NH + i];
    if (T0) {
        size_t tb = (size_t)c[b] * NH3;
        gir += T0[tb + i];
        giz += T0[tb + NH + i];
        gin += T0[tb + 2 * NH + i];
    }
    float ghr = gh[base + i];
    float ghz = gh[base + NH + i];
    float ghn = gh[base + 2 * NH + i];
    float r  = 1.0f / (1.0f + expf(-(gir + ghr)));
    float zg = 1.0f / (1.0f + expf(-(giz + ghz)));
    float nn = tanhf(gin + r * ghn);
    float hv = h[idx];
    float hn = (1.0f - zg) * nn + zg * hv;
    h[idx] = hn;
    __nv_bfloat16 hb = __float2bfloat16(hn);
    hhi[idx] = hb;
    hlo[idx] = __float2bfloat16(hn - __bfloat162float(hb));
}

// ===================== SIMT sgemm for per-launch precompute =================
__global__ __launch_bounds__(256, 2)
void sgemm128(int K,
              const float* __restrict__ A, int lda,
              const float* __restrict__ B, int ldb,
              const float* __restrict__ bias,
              float* __restrict__ Cm, int ldc)
{
    __shared__ float As[16 * 132];
    __shared__ float Bs[16 * 132];
    const int tid = threadIdx.x;
    const int bn = blockIdx.x * 128;
    const int bm = blockIdx.y * 128;
    const int lr = tid >> 2;
    const int lk = (tid & 3) << 2;
    const float* Ap = A + (size_t)(bm + lr) * lda + lk;
    const float* Bp = B + (size_t)(bn + lr) * ldb + lk;
    const int tx = tid & 15;
    const int ty = tid >> 4;
    float acc[8][8];
#pragma unroll
    for (int i = 0; i < 8; i++)
#pragma unroll
        for (int j = 0; j < 8; j++) acc[i][j] = 0.0f;
    float4 pa0 = *(const float4*)Ap;
    float4 pa1 = *(const float4*)(Ap + (size_t)64 * lda);
    float4 pb0 = *(const float4*)Bp;
    float4 pb1 = *(const float4*)(Bp + (size_t)64 * ldb);
    const int ntiles = K >> 4;
    for (int tk = 0; tk < ntiles; ++tk) {
        As[(lk + 0) * 132 + lr] = pa0.x; As[(lk + 1) * 132 + lr] = pa0.y;
        As[(lk + 2) * 132 + lr] = pa0.z; As[(lk + 3) * 132 + lr] = pa0.w;
        As[(lk + 0) * 132 + lr + 64] = pa1.x; As[(lk + 1) * 132 + lr + 64] = pa1.y;
        As[(lk + 2) * 132 + lr + 64] = pa1.z; As[(lk + 3) * 132 + lr + 64] = pa1.w;
        Bs[(lk + 0) * 132 + lr] = pb0.x; Bs[(lk + 1) * 132 + lr] = pb0.y;
        Bs[(lk + 2) * 132 + lr] = pb0.z; Bs[(lk + 3) * 132 + lr] = pb0.w;
        Bs[(lk + 0) * 132 + lr + 64] = pb1.x; Bs[(lk + 1) * 132 + lr + 64] = pb1.y;
        Bs[(lk + 2) * 132 + lr + 64] = pb1.z; Bs[(lk + 3) * 132 + lr + 64] = pb1.w;
        __syncthreads();
        if (tk + 1 < ntiles) {
            const float* An = Ap + (tk + 1) * 16;
            const float* Bn = Bp + (tk + 1) * 16;
            pa0 = *(const float4*)An; pa1 = *(const float4*)(An + (size_t)64 * lda);
            pb0 = *(const float4*)Bn; pb1 = *(const float4*)(Bn + (size_t)64 * ldb);
        }
#pragma unroll
        for (int k = 0; k < 16; ++k) {
            float4 a0 = *(const float4*)&As[k * 132 + ty * 8];
            float4 a1 = *(const float4*)&As[k * 132 + ty * 8 + 4];
            float4 b0 = *(const float4*)&Bs[k * 132 + tx * 8];
            float4 b1 = *(const float4*)&Bs[k * 132 + tx * 8 + 4];
            float av[8] = {a0.x, a0.y, a0.z, a0.w, a1.x, a1.y, a1.z, a1.w};
            float bv[8] = {b0.x, b0.y, b0.z, b0.w, b1.x, b1.y, b1.z, b1.w};
#pragma unroll
            for (int i = 0; i < 8; i++)
#pragma unroll
                for (int j = 0; j < 8; j++)
                    acc[i][j] += av[i] * bv[j];
        }
        __syncthreads();
    }
    float bb[8];
#pragma unroll
    for (int j = 0; j < 8; j++) bb[j] = bias ? bias[bn + tx * 8 + j] : 0.0f;
#pragma unroll
    for (int i = 0; i < 8; i++) {
        float* Cp = Cm + (size_t)(bm + ty * 8 + i) * ldc + bn + tx * 8;
        *(float4*)Cp = make_float4(acc[i][0] + bb[0], acc[i][1] + bb[1],
                                   acc[i][2] + bb[2], acc[i][3] + bb[3]);
        *(float4*)(Cp + 4) = make_float4(acc[i][4] + bb[4], acc[i][5] + bb[5],
                                         acc[i][6] + bb[6], acc[i][7] + bb[7]);
    }
}

// ===================== mma.sync bf16 split GEMM =============================
// C[M,N] = [Ah|Ah|Al] @ [Bh|Bl|Bh]^T over virtual K=3072.
// CTA BMx128 (BM = MT*32), BK=64, 3-stage cp.async, 8 warps (2 M x 4 N).
#define SMOFF(r, c) ((r) * 128 + ((((c) ^ ((r) & 7)) << 4)))

__device__ __forceinline__ uint32_t smem_u32(const void* p) {
    uint32_t a;
    asm("{ .reg .u64 t; cvta.to.shared.u64 t, %1; cvt.u32.u64 %0, t; }"
        : "=r"(a) : "l"(p));
    return a;
}
__device__ __forceinline__ void cp16(uint32_t dst, const void* src) {
    asm volatile("cp.async.cg.shared.global [%0], [%1], 16;"
                 :: "r"(dst), "l"(src));
}
__device__ __forceinline__ void ldm_x4(uint32_t* r, uint32_t addr) {
    asm volatile("ldmatrix.sync.aligned.m8n8.x4.shared.b16 {%0,%1,%2,%3}, [%4];"
                 : "=r"(r[0]), "=r"(r[1]), "=r"(r[2]), "=r"(r[3]) : "r"(addr));
}
__device__ __forceinline__ void mma16816(float* c, const uint32_t* a, const uint32_t* b) {
    asm volatile("mma.sync.aligned.m16n8k16.row.col.f32.bf16.bf16.f32 "
                 "{%0,%1,%2,%3}, {%4,%5,%6,%7}, {%8,%9}, {%0,%1,%2,%3};"
                 : "+f"(c[0]), "+f"(c[1]), "+f"(c[2]), "+f"(c[3])
                 : "r"(a[0]), "r"(a[1]), "r"(a[2]), "r"(b[0]), "r"(b[1]),
                   "r"(a[3]));
}
// NOTE: operand order must be a0..a3 then b0,b1 — fix inline below.
__device__ __forceinline__ void mma16816f(float* c, const uint32_t* a, const uint32_t* b) {
    asm volatile("mma.sync.aligned.m16n8k16.row.col.f32.bf16.bf16.f32 "
                 "{%0,%1,%2,%3}, {%4,%5,%6,%7}, {%8,%9}, {%0,%1,%2,%3};"
                 : "+f"(c[0]), "+f"(c[1]), "+f"(c[2]), "+f"(c[3])
                 : "r"(a[0]), "r"(a[1]), "r"(a[2]), "r"(a[3]), "r"(b[0]), "r"(b[1]));
}

// stage load: A tile BM x 64 bf16 + B tile 128 x 64 bf16
template<int MT>
__device__ __forceinline__ void issue_stage(
    uint32_t sm_stage, const __nv_bfloat16* Abase, const __nv_bfloat16* Bbase,
    int bm, int bn, int colH, int tid)
{
    constexpr int TPR = 8 / MT;          // threads per A row
    int r  = tid / TPR;
    int c0 = (tid % TPR) * MT;
    const __nv_bfloat16* ag = Abase + (size_t)(bm + r) * NH + colH + c0 * 8;
#pragma unroll
    for (int j = 0; j < MT; ++j)
        cp16(sm_stage + SMOFF(r, c0 + j), ag + j * 8);
    int r2 = tid >> 1, d0 = (tid & 1) * 4;
    const __nv_bfloat16* bg = Bbase + (size_t)(bn + r2) * NH + colH + d0 * 8;
    uint32_t sB = sm_stage + MT * 4096;
#pragma unroll
    for (int j = 0; j < 4; ++j)
        cp16(sB + SMOFF(r2, d0 + j), bg + j * 8);
}

template<int MT>
__device__ __forceinline__ void mma_mainloop(
    const __nv_bfloat16* __restrict__ Ahi, const __nv_bfloat16* __restrict__ Alo,
    const __nv_bfloat16* __restrict__ Bhi, const __nv_bfloat16* __restrict__ Blo,
    int bm, int bn, char* smem, float (&acc)[MT][4][4])
{
    constexpr int STB = MT * 4096 + 16384;
    const int tid = threadIdx.x;
    const int wid = tid >> 5, l = tid & 31;
    const int wm = wid >> 2, wn = wid & 3;
    uint32_t sbase = smem_u32(smem);

#pragma unroll
    for (int mt = 0; mt < MT; ++mt)
#pragma unroll
        for (int nt = 0; nt < 4; ++nt)
#pragma unroll
            for (int e = 0; e < 4; ++e) acc[mt][nt][e] = 0.0f;

    issue_stage<MT>(sbase, Ahi, Bhi, bm, bn, 0, tid);
    asm volatile("cp.async.commit_group;");
    issue_stage<MT>(sbase + STB, Ahi, Bhi, bm, bn, 64, tid);
    asm volatile("cp.async.commit_group;");

#pragma unroll 1
    for (int kc = 0; kc < KCH; ++kc) {
        asm volatile("cp.async.wait_group 1;");
        __syncthreads();
        int kn = kc + 2;
        if (kn < KCH) {
            const __nv_bfloat16* Ab = (kn < 32) ? Ahi : Alo;
            const __nv_bfloat16* Bb = (kn >= 16 && kn < 32) ? Blo : Bhi;
            issue_stage<MT>(sbase + (kn % 3) * STB, Ab, Bb, bm, bn,
                            (kn & 15) << 6, tid);
        }
        asm volatile("cp.async.commit_group;");

        uint32_t sA = sbase + (kc % 3) * STB;
        uint32_t sB = sA + MT * 4096;
#pragma unroll
        for (int kt = 0; kt < 4; ++kt) {
            uint32_t af[MT][4];
#pragma unroll
            for (int mt = 0; mt < MT; ++mt) {
                int row = wm * (MT * 16) + mt * 16 + (l & 15);
                ldm_x4(af[mt], sA + SMOFF(row, kt * 2 + (l >> 4)));
            }
            uint32_t bfr[4][2];
#pragma unroll
            for (int ntp = 0; ntp < 2; ++ntp) {
                int g = l >> 3;
                int nrow = wn * 32 + ntp * 16 + ((g >> 1) << 3) + (l & 7);
                uint32_t rr[4];
                ldm_x4(rr, sB + SMOFF(nrow, kt * 2 + (g & 1)));
                bfr[2 * ntp][0] = rr[0]; bfr[2 * ntp][1] = rr[1];
                bfr[2 * ntp + 1][0] = rr[2]; bfr[2 * ntp + 1][1] = rr[3];
            }
#pragma unroll
            for (int mt = 0; mt < MT; ++mt)
#pragma unroll
                for (int nt = 0; nt < 4; ++nt)
                    mma16816f(acc[mt][nt], af[mt], bfr[nt]);
        }
        __syncthreads();
    }
    asm volatile("cp.async.wait_group 0;");
}

__global__ __launch_bounds__(256, 2)
void gemm_big_mma(const __nv_bfloat16* __restrict__ Ahi, const __nv_bfloat16* __restrict__ Alo,
                  const __nv_bfloat16* __restrict__ Bhi, const __nv_bfloat16* __restrict__ Blo,
                  const float* __restrict__ bias, float* __restrict__ C)
{
    extern __shared__ char smem[];
    const int bn = blockIdx.x * 128, bm = blockIdx.y * 128;
    const int tid = threadIdx.x;
    const int wid = tid >> 5, l = tid & 31;
    const int wm = wid >> 2, wn = wid & 3;
    float acc[4][4][4];
    mma_mainloop<4>(Ahi, Alo, Bhi, Blo, bm, bn, smem, acc);

#pragma unroll
    for (int mt = 0; mt < 4; ++mt) {
#pragma unroll
        for (int nt = 0; nt < 4; ++nt) {
            int row = bm + wm * 64 + mt * 16 + (l >> 2);
            int col = bn + wn * 32 + nt * 8 + ((l & 3) << 1);
            float b0 = bias[col], b1 = bias[col + 1];
            *(float2*)&C[(size_t)row * NH3 + col] =
                make_float2(acc[mt][nt][0] + b0, acc[mt][nt][1] + b1);
            *(float2*)&C[(size_t)(row + 8) * NH3 + col] =
                make_float2(acc[mt][nt][2] + b0, acc[mt][nt][3] + b1);
        }
    }
}

// h2o: BM=32 tiles -> 128 CTAs; fused OutZ add + out write + argmax
__global__ __launch_bounds__(256)
void h2o_mma_kernel(const __nv_bfloat16* __restrict__ Ahi, const __nv_bfloat16* __restrict__ Alo,
                    const __nv_bfloat16* __restrict__ Whi, const __nv_bfloat16* __restrict__ Wlo,
                    const float* __restrict__ OutZ,
                    float* __restrict__ out, int t, int* __restrict__ cbuf)
{
    extern __shared__ char smem[];
    const int bm = blockIdx.x * 32;
    const int tid = threadIdx.x;
    const int wid = tid >> 5, l = tid & 31;
    const int wm = wid >> 2, wn = wid & 3;
    float acc[1][4][4];
    mma_mainloop<1>(Ahi, Alo, Whi, Wlo, bm, 0, smem, acc);
    __syncthreads();  // all warps done with stage smem before logits reuse

    float* lg = (float*)smem;   // [32][132]
#pragma unroll
    for (int nt = 0; nt < 4; ++nt) {
        int rl = wm * 16 + (l >> 2);
        int cl = wn * 32 + nt * 8 + ((l & 3) << 1);
        lg[rl * 132 + cl]           = acc[0][nt][0];
        lg[rl * 132 + cl + 1]       = acc[0][nt][1];
        lg[(rl + 8) * 132 + cl]     = acc[0][nt][2];
        lg[(rl + 8) * 132 + cl + 1] = acc[0][nt][3];
    }
    __syncthreads();

    if (tid < 32) {
        int row = bm + tid;
        const float* oz = OutZ + (size_t)row * NCHAR;
        float* op = out + (size_t)row * (NSTEP * NCHAR) + t * NCHAR;
        float best = -FLT_MAX;
        int bi = 0;
#pragma unroll 4
        for (int c = 0; c < NCHAR; ++c) {
            float v = lg[tid * 132 + c] + oz[c];
            op[c] = v;
            if (v > best) { best = v; bi = c; }
        }
        cbuf[row] = bi;
    }
}

// ===================== launch ===============================================
extern "C" void kernel_launch(void* const* d_in, const int* in_sizes, int n_in,
                              void* d_out, int out_size)
{
    const float* z       = (const float*)d_in[0];
    const float* embed_w = (const float*)d_in[1];
    const float* z2h_w   = (const float*)d_in[2];
    const float* z2h_b   = (const float*)d_in[3];
    const float* w_ih0   = (const float*)d_in[4];
    const float* w_hh0   = (const float*)d_in[5];
    const float* b_ih0   = (const float*)d_in[6];
    const float* b_hh0   = (const float*)d_in[7];
    const float* w_ih1   = (const float*)d_in[8];
    const float* w_hh1   = (const float*)d_in[9];
    const float* b_ih1   = (const float*)d_in[10];
    const float* b_hh1   = (const float*)d_in[11];
    const float* h2o_w   = (const float*)d_in[12];
    const float* h2o_b   = (const float*)d_in[13];
    float* out = (float*)d_out;

    float *Z0, *T0, *Esw, *OutZ, *h1, *h2, *bufA, *bufB;
    int* cbuf;
    __nv_bfloat16 *h1hi, *h1lo, *h2hi, *h2lo;
    __nv_bfloat16 *Whh0hi, *Whh0lo, *Wih1hi, *Wih1lo, *Whh1hi, *Whh1lo, *Wouthi, *Woutlo;
    cudaGetSymbolAddress((void**)&Z0,   g_Z0);
    cudaGetSymbolAddress((void**)&T0,   g_T0);
    cudaGetSymbolAddress((void**)&Esw,  g_Esw);
    cudaGetSymbolAddress((void**)&OutZ, g_OutZ);
    cudaGetSymbolAddress((void**)&h1,   g_h1);
    cudaGetSymbolAddress((void**)&h2,   g_h2);
    cudaGetSymbolAddress((void**)&bufA, g_bufA);
    cudaGetSymbolAddress((void**)&bufB, g_bufB);
    cudaGetSymbolAddress((void**)&cbuf, g_c);
    cudaGetSymbolAddress((void**)&h1hi, g_h1hi);
    cudaGetSymbolAddress((void**)&h1lo, g_h1lo);
    cudaGetSymbolAddress((void**)&h2hi, g_h2hi);
    cudaGetSymbolAddress((void**)&h2lo, g_h2lo);
    cudaGetSymbolAddress((void**)&Whh0hi, g_Whh0hi);
    cudaGetSymbolAddress((void**)&Whh0lo, g_Whh0lo);
    cudaGetSymbolAddress((void**)&Wih1hi, g_Wih1hi);
    cudaGetSymbolAddress((void**)&Wih1lo, g_Wih1lo);
    cudaGetSymbolAddress((void**)&Whh1hi, g_Whh1hi);
    cudaGetSymbolAddress((void**)&Whh1lo, g_Whh1lo);
    cudaGetSymbolAddress((void**)&Wouthi, g_Wouthi);
    cudaGetSymbolAddress((void**)&Woutlo, g_Woutlo);

    const int smem_big = 3 * (4 * 4096 + 16384);  // 98304
    const int smem_h2o = 3 * (1 * 4096 + 16384);  // 61440
    cudaFuncSetAttribute(gemm_big_mma, cudaFuncAttributeMaxDynamicSharedMemorySize, smem_big);
    cudaFuncSetAttribute(h2o_mma_kernel, cudaFuncAttributeMaxDynamicSharedMemorySize, smem_h2o);

    // ---- per-replay precompute ----
    init_c_kernel<<<(BATCH + 255) / 256, 256>>>(cbuf);
    swish_kernel<<<(NCHAR * NH + 255) / 256, 256>>>(embed_w, Esw, NCHAR * NH);
    sgemm128<<<dim3(NH3 / 128, 1), 256>>>(NH, Esw, NH, w_ih0, LDW, nullptr, T0, NH3);
    sgemm128<<<dim3(NH3 / 128, BATCH / 128), 256>>>(NLAT, z, NLAT, w_ih0 + NH, LDW, b_ih0, Z0, NH3);
    sgemm128<<<dim3(1, BATCH / 128), 256>>>(NLAT, z, NLAT, h2o_w + NH, LDW, h2o_b, OutZ, NCHAR);
    sgemm128<<<dim3(NH / 128, BATCH / 128), 256>>>(NLAT, z, NLAT, z2h_w, NLAT, z2h_b, h1, NH);
    sgemm128<<<dim3(NH / 128, BATCH / 128), 256>>>(NLAT, z, NLAT, z2h_w, NLAT, z2h_b, h2, NH);
    // splits
    split_kernel<<<BATCH * NH / 256, 256>>>(h1, NH, h1hi, h1lo, BATCH * NH);
    split_kernel<<<BATCH * NH / 256, 256>>>(h2, NH, h2hi, h2lo, BATCH * NH);
    split_kernel<<<NH3 * NH / 256, 256>>>(w_hh0, NH, Whh0hi, Whh0lo, NH3 * NH);
    split_kernel<<<NH3 * NH / 256, 256>>>(w_ih1, NH, Wih1hi, Wih1lo, NH3 * NH);
    split_kernel<<<NH3 * NH / 256, 256>>>(w_hh1, NH, Whh1hi, Whh1lo, NH3 * NH);
    split_kernel<<<NCHAR * NH / 256, 256>>>(h2o_w, LDW, Wouthi, Woutlo, NCHAR * NH);

    dim3 gbig(NH3 / 128, BATCH / 128);   // 24 x 32

    // ---- 64 recurrent steps ----
    for (int t = 0; t < NSTEP; ++t) {
        gemm_big_mma<<<gbig, 256, smem_big>>>(h1hi, h1lo, Whh0hi, Whh0lo, b_hh0, bufA);
        gru_gates_kernel<<<BATCH * NH / 256, 256>>>(Z0, T0, cbuf, bufA, h1, h1hi, h1lo);
        gemm_big_mma<<<gbig, 256, smem_big>>>(h1hi, h1lo, Wih1hi, Wih1lo, b_ih1, bufA);
        gemm_big_mma<<<gbig, 256, smem_big>>>(h2hi, h2lo, Whh1hi, Whh1lo, b_hh1, bufB);
        gru_gates_kernel<<<BATCH * NH / 256, 256>>>(bufA, nullptr, nullptr, bufB, h2, h2hi, h2lo);
        h2o_mma_kernel<<<BATCH / 32, 256, smem_h2o>>>(h2hi, h2lo, Wouthi, Woutlo,
                                                      OutZ, out, t, cbuf);
    }
}

// round 7
// speedup vs baseline: 3.5108x; 1.0499x over previous
#include <cuda_runtime.h>
#include <cuda_bf16.h>
#include <math.h>
#include <float.h>
#include <stdint.h>

#define BATCH 4096
#define NLAT  256
#define NCHAR 128
#define NH    1024
#define NH3   3072
#define NSTEP 64
#define LDW   1280   // H + L, row stride of w_ih0 / h2o_w
#define KCH   48     // virtual K chunks of 64 (3 x 1024/64)

// gate-interleaved column permutation: col' for (gate g, unit u)
#define PERMC(g, u) (96 * ((u) >> 5) + 32 * (g) + ((u) & 31))

// ===================== scratch (device globals) =============================
__device__ float g_Z0[BATCH * NH3];      // permuted layout
__device__ float g_T0[NCHAR * NH3];      // permuted layout
__device__ float g_Esw[NCHAR * NH];
__device__ float g_OutZ[BATCH * NCHAR];
__device__ float g_h1[BATCH * NH];
__device__ float g_h2[BATCH * NH];
__device__ float g_bufA[BATCH * NH3];    // gi1, permuted layout
__device__ int   g_c[BATCH];
__device__ float g_bih0p[NH3], g_bhh0p[NH3], g_bih1p[NH3], g_bhh1p[NH3];
// bf16 hi/lo splits (16B-aligned for cp.async)
__device__ __align__(16) __nv_bfloat16 g_h1hi[BATCH * NH], g_h1lo[BATCH * NH];
__device__ __align__(16) __nv_bfloat16 g_h2hi[BATCH * NH], g_h2lo[BATCH * NH];
__device__ __align__(16) __nv_bfloat16 g_Whh0hi[NH3 * NH], g_Whh0lo[NH3 * NH]; // permuted rows
__device__ __align__(16) __nv_bfloat16 g_Wih1hi[NH3 * NH], g_Wih1lo[NH3 * NH]; // permuted rows
__device__ __align__(16) __nv_bfloat16 g_Whh1hi[NH3 * NH], g_Whh1lo[NH3 * NH]; // permuted rows
__device__ __align__(16) __nv_bfloat16 g_Wouthi[NCHAR * NH], g_Woutlo[NCHAR * NH];

// ===================== small kernels ========================================
__global__ void init_c_kernel(int* __restrict__ c) {
    int i = blockIdx.x * blockDim.x + threadIdx.x;
    if (i < BATCH) c[i] = 0;
}
__global__ void swish_kernel(const float* __restrict__ e, float* __restrict__ o, int n) {
    int i = blockIdx.x * blockDim.x + threadIdx.x;
    if (i < n) { float v = e[i]; o[i] = v / (1.0f + expf(-v)); }
}
__global__ void permbias_kernel(const float* __restrict__ src, float* __restrict__ dst) {
    int i = blockIdx.x * blockDim.x + threadIdx.x;
    if (i < NH3) {
        int g = i >> 10, u = i & 1023;
        dst[PERMC(g, u)] = src[i];
    }
}
// plain split: fp32[rows,1024] (row stride) -> bf16 hi/lo contiguous
__global__ void split_kernel(const float* __restrict__ src, int stride,
                             __nv_bfloat16* __restrict__ hi,
                             __nv_bfloat16* __restrict__ lo, int total) {
    int i = blockIdx.x * blockDim.x + threadIdx.x;
    if (i < total) {
        int r = i >> 10, cc = i & 1023;
        float v = src[(size_t)r * stride + cc];
        __nv_bfloat16 h = __float2bfloat16(v);
        hi[i] = h;
        lo[i] = __float2bfloat16(v - __bfloat162float(h));
    }
}
// permuted split for [3072,1024] gate weights: dst row = PERMC(g,u)
__global__ void split_perm_kernel(const float* __restrict__ src,
                                  __nv_bfloat16* __restrict__ hi,
                                  __nv_bfloat16* __restrict__ lo) {
    int i = blockIdx.x * blockDim.x + threadIdx.x;
    if (i < NH3 * NH) {
        int r = i >> 10, cc = i & 1023;
        int g = r >> 10, u = r & 1023;
        int dr = PERMC(g, u);
        float v = src[(size_t)r * NH + cc];
        __nv_bfloat16 h = __float2bfloat16(v);
        hi[(size_t)dr * NH + cc] = h;
        lo[(size_t)dr * NH + cc] = __float2bfloat16(v - __bfloat162float(h));
    }
}

// ===================== SIMT sgemm for per-launch precompute =================
// C = A*B^T (+bias). permB: B-row index mapped through inverse gate permutation.
__global__ __launch_bounds__(256, 2)
void sgemm128(int K,
              const float* __restrict__ A, int lda,
              const float* __restrict__ B, int ldb,
              const float* __restrict__ bias,
              float* __restrict__ Cm, int ldc, int permB)
{
    __shared__ float As[16 * 132];
    __shared__ float Bs[16 * 132];
    const int tid = threadIdx.x;
    const int bn = blockIdx.x * 128;
    const int bm = blockIdx.y * 128;
    const int lr = tid >> 2;
    const int lk = (tid & 3) << 2;
    int n1 = bn + lr, n2 = bn + lr + 64;
    if (permB) {
        int r1 = n1 % 96, r2 = n2 % 96;
        n1 = (r1 / 32) * 1024 + (n1 / 96) * 32 + (r1 % 32);
        n2 = (r2 / 32) * 1024 + (n2 / 96) * 32 + (r2 % 32);
    }
    const float* Ap  = A + (size_t)(bm + lr) * lda + lk;
    const float* Ap2 = A + (size_t)(bm + lr + 64) * lda + lk;
    const float* Bp  = B + (size_t)n1 * ldb + lk;
    const float* Bp2 = B + (size_t)n2 * ldb + lk;
    const int tx = tid & 15;
    const int ty = tid >> 4;
    float acc[8][8];
#pragma unroll
    for (int i = 0; i < 8; i++)
#pragma unroll
        for (int j = 0; j < 8; j++) acc[i][j] = 0.0f;
    float4 pa0 = *(const float4*)Ap;
    float4 pa1 = *(const float4*)Ap2;
    float4 pb0 = *(const float4*)Bp;
    float4 pb1 = *(const float4*)Bp2;
    const int ntiles = K >> 4;
    for (int tk = 0; tk < ntiles; ++tk) {
        As[(lk + 0) * 132 + lr] = pa0.x; As[(lk + 1) * 132 + lr] = pa0.y;
        As[(lk + 2) * 132 + lr] = pa0.z; As[(lk + 3) * 132 + lr] = pa0.w;
        As[(lk + 0) * 132 + lr + 64] = pa1.x; As[(lk + 1) * 132 + lr + 64] = pa1.y;
        As[(lk + 2) * 132 + lr + 64] = pa1.z; As[(lk + 3) * 132 + lr + 64] = pa1.w;
        Bs[(lk + 0) * 132 + lr] = pb0.x; Bs[(lk + 1) * 132 + lr] = pb0.y;
        Bs[(lk + 2) * 132 + lr] = pb0.z; Bs[(lk + 3) * 132 + lr] = pb0.w;
        Bs[(lk + 0) * 132 + lr + 64] = pb1.x; Bs[(lk + 1) * 132 + lr + 64] = pb1.y;
        Bs[(lk + 2) * 132 + lr + 64] = pb1.z; Bs[(lk + 3) * 132 + lr + 64] = pb1.w;
        __syncthreads();
        if (tk + 1 < ntiles) {
            pa0 = *(const float4*)(Ap  + (tk + 1) * 16);
            pa1 = *(const float4*)(Ap2 + (tk + 1) * 16);
            pb0 = *(const float4*)(Bp  + (tk + 1) * 16);
            pb1 = *(const float4*)(Bp2 + (tk + 1) * 16);
        }
#pragma unroll
        for (int k = 0; k < 16; ++k) {
            float4 a0 = *(const float4*)&As[k * 132 + ty * 8];
            float4 a1 = *(const float4*)&As[k * 132 + ty * 8 + 4];
            float4 b0 = *(const float4*)&Bs[k * 132 + tx * 8];
            float4 b1 = *(const float4*)&Bs[k * 132 + tx * 8 + 4];
            float av[8] = {a0.x, a0.y, a0.z, a0.w, a1.x, a1.y, a1.z, a1.w};
            float bv[8] = {b0.x, b0.y, b0.z, b0.w, b1.x, b1.y, b1.z, b1.w};
#pragma unroll
            for (int i = 0; i < 8; i++)
#pragma unroll
                for (int j = 0; j < 8; j++)
                    acc[i][j] += av[i] * bv[j];
        }
        __syncthreads();
    }
    float bb[8];
#pragma unroll
    for (int j = 0; j < 8; j++) bb[j] = bias ? bias[bn + tx * 8 + j] : 0.0f;
#pragma unroll
    for (int i = 0; i < 8; i++) {
        float* Cp = Cm + (size_t)(bm + ty * 8 + i) * ldc + bn + tx * 8;
        *(float4*)Cp = make_float4(acc[i][0] + bb[0], acc[i][1] + bb[1],
                                   acc[i][2] + bb[2], acc[i][3] + bb[3]);
        *(float4*)(Cp + 4) = make_float4(acc[i][4] + bb[4], acc[i][5] + bb[5],
                                         acc[i][6] + bb[6], acc[i][7] + bb[7]);
    }
}

// ===================== mma.sync bf16 split GEMM core ========================
#define SMOFF(r, c) ((r) * 128 + ((((c) ^ ((r) & 7)) << 4)))

__device__ __forceinline__ uint32_t smem_u32(const void* p) {
    uint32_t a;
    asm("{ .reg .u64 t; cvta.to.shared.u64 t, %1; cvt.u32.u64 %0, t; }"
        : "=r"(a) : "l"(p));
    return a;
}
__device__ __forceinline__ void cp16(uint32_t dst, const void* src) {
    asm volatile("cp.async.cg.shared.global [%0], [%1], 16;"
                 :: "r"(dst), "l"(src));
}
__device__ __forceinline__ void ldm_x4(uint32_t* r, uint32_t addr) {
    asm volatile("ldmatrix.sync.aligned.m8n8.x4.shared.b16 {%0,%1,%2,%3}, [%4];"
                 : "=r"(r[0]), "=r"(r[1]), "=r"(r[2]), "=r"(r[3]) : "r"(addr));
}
__device__ __forceinline__ void ldm_x2(uint32_t* r, uint32_t addr) {
    asm volatile("ldmatrix.sync.aligned.m8n8.x2.shared.b16 {%0,%1}, [%2];"
                 : "=r"(r[0]), "=r"(r[1]) : "r"(addr));
}
__device__ __forceinline__ void mma16816f(float* c, const uint32_t* a, const uint32_t* b) {
    asm volatile("mma.sync.aligned.m16n8k16.row.col.f32.bf16.bf16.f32 "
                 "{%0,%1,%2,%3}, {%4,%5,%6,%7}, {%8,%9}, {%0,%1,%2,%3};"
                 : "+f"(c[0]), "+f"(c[1]), "+f"(c[2]), "+f"(c[3])
                 : "r"(a[0]), "r"(a[1]), "r"(a[2]), "r"(a[3]), "r"(b[0]), "r"(b[1]));
}

// stage load: A tile (MT*32) x 64 bf16 + B tile NB x 64 bf16
template<int MT, int NB>
__device__ __forceinline__ void issue_stage(
    uint32_t sm_stage, const __nv_bfloat16* Abase, const __nv_bfloat16* Bbase,
    int bm, int bn, int colH, int tid)
{
    constexpr int TPR = 8 / MT;
    int r  = tid / TPR;
    int c0 = (tid % TPR) * MT;
    const __nv_bfloat16* ag = Abase + (size_t)(bm + r) * NH + colH + c0 * 8;
#pragma unroll
    for (int j = 0; j < MT; ++j)
        cp16(sm_stage + SMOFF(r, c0 + j), ag + j * 8);
    uint32_t sB = sm_stage + MT * 4096;
    if (NB == 128 || tid < 2 * NB) {
        int r2 = tid >> 1, d0 = (tid & 1) * 4;
        const __nv_bfloat16* bg = Bbase + (size_t)(bn + r2) * NH + colH + d0 * 8;
#pragma unroll
        for (int j = 0; j < 4; ++j)
            cp16(sB + SMOFF(r2, d0 + j), bg + j * 8);
    }
}

// NT n-tiles of 8 per warp; warp grid 2 (M) x 4 (N)
template<int MT, int NB, int NT>
__device__ __forceinline__ void mma_mainloop(
    const __nv_bfloat16* __restrict__ Ahi, const __nv_bfloat16* __restrict__ Alo,
    const __nv_bfloat16* __restrict__ Bhi, const __nv_bfloat16* __restrict__ Blo,
    int bm, int bn, char* smem, float (&acc)[MT][NT][4])
{
    constexpr int STB = MT * 4096 + NB * 128;
    const int tid = threadIdx.x;
    const int wid = tid >> 5, l = tid & 31;
    const int wm = wid >> 2, wn = wid & 3;
    uint32_t sbase = smem_u32(smem);

#pragma unroll
    for (int mt = 0; mt < MT; ++mt)
#pragma unroll
        for (int nt = 0; nt < NT; ++nt)
#pragma unroll
            for (int e = 0; e < 4; ++e) acc[mt][nt][e] = 0.0f;

    issue_stage<MT, NB>(sbase, Ahi, Bhi, bm, bn, 0, tid);
    asm volatile("cp.async.commit_group;");
    issue_stage<MT, NB>(sbase + STB, Ahi, Bhi, bm, bn, 64, tid);
    asm volatile("cp.async.commit_group;");

#pragma unroll 1
    for (int kc = 0; kc < KCH; ++kc) {
        asm volatile("cp.async.wait_group 1;");
        __syncthreads();
        int kn = kc + 2;
        if (kn < KCH) {
            const __nv_bfloat16* Ab = (kn < 32) ? Ahi : Alo;
            const __nv_bfloat16* Bb = (kn >= 16 && kn < 32) ? Blo : Bhi;
            issue_stage<MT, NB>(sbase + (kn % 3) * STB, Ab, Bb, bm, bn,
                                (kn & 15) << 6, tid);
        }
        asm volatile("cp.async.commit_group;");

        uint32_t sA = sbase + (kc % 3) * STB;
        uint32_t sB = sA + MT * 4096;
#pragma unroll
        for (int kt = 0; kt < 4; ++kt) {
            uint32_t af[MT][4];
#pragma unroll
            for (int mt = 0; mt < MT; ++mt) {
                int row = wm * (MT * 16) + mt * 16 + (l & 15);
                ldm_x4(af[mt], sA + SMOFF(row, kt * 2 + (l >> 4)));
            }
            uint32_t bfr[NT][2];
            if (NT == 4) {
#pragma unroll
                for (int ntp = 0; ntp < 2; ++ntp) {
                    int g = l >> 3;
                    int nrow = wn * 32 + ntp * 16 + ((g >> 1) << 3) + (l & 7);
                    uint32_t rr[4];
                    ldm_x4(rr, sB + SMOFF(nrow, kt * 2 + (g & 1)));
                    bfr[2 * ntp][0] = rr[0]; bfr[2 * ntp][1] = rr[1];
                    bfr[2 * ntp + 1][0] = rr[2]; bfr[2 * ntp + 1][1] = rr[3];
                }
            } else {
#pragma unroll
                for (int nt = 0; nt < NT; ++nt) {
                    int n0 = wn * (NT * 8) + nt * 8;
                    ldm_x2(bfr[nt], sB + SMOFF(n0 + (l & 7), kt * 2 + ((l >> 3) & 1)));
                }
            }
#pragma unroll
            for (int mt = 0; mt < MT; ++mt)
#pragma unroll
                for (int nt = 0; nt < NT; ++nt)
                    mma16816f(acc[mt][nt], af[mt], bfr[nt]);
        }
    }
    asm volatile("cp.async.wait_group 0;");
}

// ===================== big GEMM, BN=96, optional fused GRU gates ============
// MODE 0: C = A@B^T + biasP (write bufA, permuted cols)
// MODE 1: layer-0 gates: gi = Z0p + T0p[c];  h,hi,lo updated
// MODE 2: layer-1 gates: gi = bufA (bias already included)
template<int MODE>
__global__ __launch_bounds__(256, 2)
void gemm96(const __nv_bfloat16* __restrict__ Ahi, const __nv_bfloat16* __restrict__ Alo,
            const __nv_bfloat16* __restrict__ Bhi, const __nv_bfloat16* __restrict__ Blo,
            const float* __restrict__ biasP,
            const float* __restrict__ gi, const float* __restrict__ T0,
            const int* __restrict__ cptr,
            float* __restrict__ hO,
            __nv_bfloat16* __restrict__ hhi, __nv_bfloat16* __restrict__ hlo,
            float* __restrict__ Cout)
{
    extern __shared__ char smem[];
    const int bn = blockIdx.x * 96, bm = blockIdx.y * 128;
    const int tid = threadIdx.x;
    const int wid = tid >> 5, l = tid & 31;
    const int wm = wid >> 2, wn = wid & 3;
    float acc[4][3][4];
    mma_mainloop<4, 96, 3>(Ahi, Alo, Bhi, Blo, bm, bn, smem, acc);

    if (MODE == 0) {
#pragma unroll
        for (int mt = 0; mt < 4; ++mt)
#pragma unroll
            for (int nt = 0; nt < 3; ++nt) {
                int row = bm + wm * 64 + mt * 16 + (l >> 2);
                int col = bn + wn * 24 + nt * 8 + ((l & 3) << 1);
                float b0 = biasP[col], b1 = biasP[col + 1];
                *(float2*)&Cout[(size_t)row * NH3 + col] =
                    make_float2(acc[mt][nt][0] + b0, acc[mt][nt][1] + b1);
                *(float2*)&Cout[(size_t)(row + 8) * NH3 + col] =
                    make_float2(acc[mt][nt][2] + b0, acc[mt][nt][3] + b1);
            }
        return;
    }

    // gates epilogue: stage C tile [128][96] in smem (stride 100)
    __syncthreads();
    float* Cs = (float*)smem;
#pragma unroll
    for (int mt = 0; mt < 4; ++mt)
#pragma unroll
        for (int nt = 0; nt < 3; ++nt) {
            int r0 = wm * 64 + mt * 16 + (l >> 2);
            int c0 = wn * 24 + nt * 8 + ((l & 3) << 1);
            Cs[r0 * 100 + c0]           = acc[mt][nt][0];
            Cs[r0 * 100 + c0 + 1]       = acc[mt][nt][1];
            Cs[(r0 + 8) * 100 + c0]     = acc[mt][nt][2];
            Cs[(r0 + 8) * 100 + c0 + 1] = acc[mt][nt][3];
        }
    __syncthreads();

    const int ul = l;                 // unit within tile (0..31)
    const int u  = bn / 3 + ul;       // global hidden unit
    float bh0 = biasP[bn + ul];
    float bh1 = biasP[bn + 32 + ul];
    float bh2 = biasP[bn + 64 + ul];
#pragma unroll 2
    for (int i = 0; i < 16; ++i) {
        int rb = wid * 16 + i;
        int b = bm + rb;
        float ghr = Cs[rb * 100 + ul] + bh0;
        float ghz = Cs[rb * 100 + 32 + ul] + bh1;
        float ghn = Cs[rb * 100 + 64 + ul] + bh2;
        const float* gp = gi + (size_t)b * NH3 + bn;
        float gir = gp[ul], giz = gp[32 + ul], gin = gp[64 + ul];
        if (MODE == 1) {
            int cb = cptr[b];
            const float* tp = T0 + (size_t)cb * NH3 + bn;
            gir += tp[ul]; giz += tp[32 + ul]; gin += tp[64 + ul];
        }
        float r  = 1.0f / (1.0f + expf(-(gir + ghr)));
        float zg = 1.0f / (1.0f + expf(-(giz + ghz)));
        float nn = tanhf(gin + r * ghn);
        size_t hidx = (size_t)b * NH + u;
        float hv = hO[hidx];
        float hn2 = (1.0f - zg) * nn + zg * hv;
        hO[hidx] = hn2;
        __nv_bfloat16 hb = __float2bfloat16(hn2);
        hhi[hidx] = hb;
        hlo[hidx] = __float2bfloat16(hn2 - __bfloat162float(hb));
    }
}

// ===================== h2o: BM=32, BN=128, fused argmax =====================
__global__ __launch_bounds__(256)
void h2o_mma_kernel(const __nv_bfloat16* __restrict__ Ahi, const __nv_bfloat16* __restrict__ Alo,
                    const __nv_bfloat16* __restrict__ Whi, const __nv_bfloat16* __restrict__ Wlo,
                    const float* __restrict__ OutZ,
                    float* __restrict__ out, int t, int* __restrict__ cbuf)
{
    extern __shared__ char smem[];
    const int bm = blockIdx.x * 32;
    const int tid = threadIdx.x;
    const int wid = tid >> 5, l = tid & 31;
    const int wm = wid >> 2, wn = wid & 3;
    float acc[1][4][4];
    mma_mainloop<1, 128, 4>(Ahi, Alo, Whi, Wlo, bm, 0, smem, acc);
    __syncthreads();

    float* lg = (float*)smem;   // [32][132]
#pragma unroll
    for (int nt = 0; nt < 4; ++nt) {
        int rl = wm * 16 + (l >> 2);
        int cl = wn * 32 + nt * 8 + ((l & 3) << 1);
        lg[rl * 132 + cl]           = acc[0][nt][0];
        lg[rl * 132 + cl + 1]       = acc[0][nt][1];
        lg[(rl + 8) * 132 + cl]     = acc[0][nt][2];
        lg[(rl + 8) * 132 + cl + 1] = acc[0][nt][3];
    }
    __syncthreads();

    if (tid < 32) {
        int row = bm + tid;
        const float* oz = OutZ + (size_t)row * NCHAR;
        float* op = out + (size_t)row * (NSTEP * NCHAR) + t * NCHAR;
        float best = -FLT_MAX;
        int bi = 0;
#pragma unroll 4
        for (int c = 0; c < NCHAR; ++c) {
            float v = lg[tid * 132 + c] + oz[c];
            op[c] = v;
            if (v > best) { best = v; bi = c; }
        }
        cbuf[row] = bi;
    }
}

// ===================== launch ===============================================
extern "C" void kernel_launch(void* const* d_in, const int* in_sizes, int n_in,
                              void* d_out, int out_size)
{
    const float* z       = (const float*)d_in[0];
    const float* embed_w = (const float*)d_in[1];
    const float* z2h_w   = (const float*)d_in[2];
    const float* z2h_b   = (const float*)d_in[3];
    const float* w_ih0   = (const float*)d_in[4];
    const float* w_hh0   = (const float*)d_in[5];
    const float* b_ih0   = (const float*)d_in[6];
    const float* b_hh0   = (const float*)d_in[7];
    const float* w_ih1   = (const float*)d_in[8];
    const float* w_hh1   = (const float*)d_in[9];
    const float* b_ih1   = (const float*)d_in[10];
    const float* b_hh1   = (const float*)d_in[11];
    const float* h2o_w   = (const float*)d_in[12];
    const float* h2o_b   = (const float*)d_in[13];
    float* out = (float*)d_out;

    float *Z0, *T0, *Esw, *OutZ, *h1, *h2, *bufA;
    float *bih0p, *bhh0p, *bih1p, *bhh1p;
    int* cbuf;
    __nv_bfloat16 *h1hi, *h1lo, *h2hi, *h2lo;
    __nv_bfloat16 *Whh0hi, *Whh0lo, *Wih1hi, *Wih1lo, *Whh1hi, *Whh1lo, *Wouthi, *Woutlo;
    cudaGetSymbolAddress((void**)&Z0,   g_Z0);
    cudaGetSymbolAddress((void**)&T0,   g_T0);
    cudaGetSymbolAddress((void**)&Esw,  g_Esw);
    cudaGetSymbolAddress((void**)&OutZ, g_OutZ);
    cudaGetSymbolAddress((void**)&h1,   g_h1);
    cudaGetSymbolAddress((void**)&h2,   g_h2);
    cudaGetSymbolAddress((void**)&bufA, g_bufA);
    cudaGetSymbolAddress((void**)&cbuf, g_c);
    cudaGetSymbolAddress((void**)&bih0p, g_bih0p);
    cudaGetSymbolAddress((void**)&bhh0p, g_bhh0p);
    cudaGetSymbolAddress((void**)&bih1p, g_bih1p);
    cudaGetSymbolAddress((void**)&bhh1p, g_bhh1p);
    cudaGetSymbolAddress((void**)&h1hi, g_h1hi);
    cudaGetSymbolAddress((void**)&h1lo, g_h1lo);
    cudaGetSymbolAddress((void**)&h2hi, g_h2hi);
    cudaGetSymbolAddress((void**)&h2lo, g_h2lo);
    cudaGetSymbolAddress((void**)&Whh0hi, g_Whh0hi);
    cudaGetSymbolAddress((void**)&Whh0lo, g_Whh0lo);
    cudaGetSymbolAddress((void**)&Wih1hi, g_Wih1hi);
    cudaGetSymbolAddress((void**)&Wih1lo, g_Wih1lo);
    cudaGetSymbolAddress((void**)&Whh1hi, g_Whh1hi);
    cudaGetSymbolAddress((void**)&Whh1lo, g_Whh1lo);
    cudaGetSymbolAddress((void**)&Wouthi, g_Wouthi);
    cudaGetSymbolAddress((void**)&Woutlo, g_Woutlo);

    const int smem_big = 3 * (4 * 4096 + 96 * 128);   // 86016
    const int smem_h2o = 3 * (1 * 4096 + 128 * 128);  // 61440
    cudaFuncSetAttribute(gemm96<0>, cudaFuncAttributeMaxDynamicSharedMemorySize, smem_big);
    cudaFuncSetAttribute(gemm96<1>, cudaFuncAttributeMaxDynamicSharedMemorySize, smem_big);
    cudaFuncSetAttribute(gemm96<2>, cudaFuncAttributeMaxDynamicSharedMemorySize, smem_big);
    cudaFuncSetAttribute(h2o_mma_kernel, cudaFuncAttributeMaxDynamicSharedMemorySize, smem_h2o);

    // ---- per-replay precompute ----
    init_c_kernel<<<(BATCH + 255) / 256, 256>>>(cbuf);
    swish_kernel<<<(NCHAR * NH + 255) / 256, 256>>>(embed_w, Esw, NCHAR * NH);
    permbias_kernel<<<(NH3 + 255) / 256, 256>>>(b_ih0, bih0p);
    permbias_kernel<<<(NH3 + 255) / 256, 256>>>(b_hh0, bhh0p);
    permbias_kernel<<<(NH3 + 255) / 256, 256>>>(b_ih1, bih1p);
    permbias_kernel<<<(NH3 + 255) / 256, 256>>>(b_hh1, bhh1p);
    // T0p = swish(embed) @ w_ih0[:, :H]^T   (permuted cols)
    sgemm128<<<dim3(NH3 / 128, 1), 256>>>(NH, Esw, NH, w_ih0, LDW, nullptr, T0, NH3, 1);
    // Z0p = z @ w_ih0[:, H:]^T + b_ih0p     (permuted cols)
    sgemm128<<<dim3(NH3 / 128, BATCH / 128), 256>>>(NLAT, z, NLAT, w_ih0 + NH, LDW, bih0p, Z0, NH3, 1);
    // OutZ = z @ h2o_w[:, H:]^T + h2o_b
    sgemm128<<<dim3(1, BATCH / 128), 256>>>(NLAT, z, NLAT, h2o_w + NH, LDW, h2o_b, OutZ, NCHAR, 0);
    // h1 = h2 = z @ z2h_w^T + z2h_b
    sgemm128<<<dim3(NH / 128, BATCH / 128), 256>>>(NLAT, z, NLAT, z2h_w, NLAT, z2h_b, h1, NH, 0);
    sgemm128<<<dim3(NH / 128, BATCH / 128), 256>>>(NLAT, z, NLAT, z2h_w, NLAT, z2h_b, h2, NH, 0);
    // splits
    split_kernel<<<BATCH * NH / 256, 256>>>(h1, NH, h1hi, h1lo, BATCH * NH);
    split_kernel<<<BATCH * NH / 256, 256>>>(h2, NH, h2hi, h2lo, BATCH * NH);
    split_perm_kernel<<<NH3 * NH / 256, 256>>>(w_hh0, Whh0hi, Whh0lo);
    split_perm_kernel<<<NH3 * NH / 256, 256>>>(w_ih1, Wih1hi, Wih1lo);
    split_perm_kernel<<<NH3 * NH / 256, 256>>>(w_hh1, Whh1hi, Whh1lo);
    split_kernel<<<NCHAR * NH / 256, 256>>>(h2o_w, LDW, Wouthi, Woutlo, NCHAR * NH);

    dim3 gbig(NH3 / 96, BATCH / 128);   // 32 x 32

    // ---- 64 recurrent steps: 4 kernels each ----
    for (int t = 0; t < NSTEP; ++t) {
        // layer 0: gh0 MMA + fused gates -> h1, splits
        gemm96<1><<<gbig, 256, smem_big>>>(h1hi, h1lo, Whh0hi, Whh0lo, bhh0p,
                                           Z0, T0, cbuf, h1, h1hi, h1lo, nullptr);
        // gi1 = h1 @ w_ih1^T + b_ih1p (permuted) -> bufA
        gemm96<0><<<gbig, 256, smem_big>>>(h1hi, h1lo, Wih1hi, Wih1lo, bih1p,
                                           nullptr, nullptr, nullptr,
                                           nullptr, nullptr, nullptr, bufA);
        // layer 1: gh1 MMA + fused gates (gi from bufA) -> h2, splits
        gemm96<2><<<gbig, 256, smem_big>>>(h2hi, h2lo, Whh1hi, Whh1lo, bhh1p,
                                           bufA, nullptr, nullptr, h2, h2hi, h2lo, nullptr);
        // logits -> out[:, t, :], argmax -> c
        h2o_mma_kernel<<<BATCH / 32, 256, smem_h2o>>>(h2hi, h2lo, Wouthi, Woutlo,
                                                      OutZ, out, t, cbuf);
    }
}

// round 9
// speedup vs baseline: 3.5528x; 1.0120x over previous
#include <cuda_runtime.h>
#include <cuda_fp16.h>
#include <math.h>
#include <float.h>
#include <stdint.h>

#define BATCH 4096
#define NLAT  256
#define NCHAR 128
#define NH    1024
#define NH3   3072
#define NSTEP 64
#define LDW   1280
#define KCH   48     // virtual K chunks of 64 (3 x 1024/64)

#define PERMC(g, u) (96 * ((u) >> 5) + 32 * (g) + ((u) & 31))

// ===================== scratch =============================================
__device__ float g_Z0[BATCH * NH3];
__device__ float g_T0[NCHAR * NH3];
__device__ float g_Esw[NCHAR * NH];
__device__ float g_OutZ[BATCH * NCHAR];
__device__ float g_h1[BATCH * NH];
__device__ float g_h2[BATCH * NH];
__device__ float g_bufB[BATCH * NH3];    // gh1, permuted
__device__ int   g_c[BATCH];
__device__ float g_bih0p[NH3], g_bhh0p[NH3], g_bih1p[NH3], g_bhh1p[NH3];
// fp16 hi/lo splits; h1 is double-buffered (race fix)
__device__ __align__(16) __half g_h1hi[2][BATCH * NH], g_h1lo[2][BATCH * NH];
__device__ __align__(16) __half g_h2hi[BATCH * NH], g_h2lo[BATCH * NH];
__device__ __align__(16) __half g_Whh0hi[NH3 * NH], g_Whh0lo[NH3 * NH];
__device__ __align__(16) __half g_Wih1hi[NH3 * NH], g_Wih1lo[NH3 * NH];
__device__ __align__(16) __half g_Whh1hi[NH3 * NH], g_Whh1lo[NH3 * NH];
__device__ __align__(16) __half g_Wouthi[NCHAR * NH], g_Woutlo[NCHAR * NH];

// ===================== prep 0: init c, swish, bias perms ====================
__global__ void prep0_kernel(const float* __restrict__ embed_w,
                             const float* __restrict__ b_ih0,
                             const float* __restrict__ b_hh0,
                             const float* __restrict__ b_ih1,
                             const float* __restrict__ b_hh1)
{
    int i = blockIdx.x * blockDim.x + threadIdx.x;
    if (i < BATCH) g_c[i] = 0;
    if (i < NH3) {
        int g = i >> 10, u = i & 1023;
        int d = PERMC(g, u);
        g_bih0p[d] = b_ih0[i];
        g_bhh0p[d] = b_hh0[i];
        g_bih1p[d] = b_ih1[i];
        g_bhh1p[d] = b_hh1[i];
    }
    if (i < NCHAR * NH) {
        float v = embed_w[i];
        g_Esw[i] = v / (1.0f + expf(-v));
    }
}

// ===================== SIMT sgemm body (precompute) =========================
__device__ void sgemm_body(int K,
                           const float* __restrict__ A, int lda,
                           const float* __restrict__ B, int ldb,
                           const float* __restrict__ bias,
                           float* __restrict__ Cm, float* __restrict__ Cm2,
                           int ldc, int permB)
{
    __shared__ float As[16 * 132];
    __shared__ float Bs[16 * 132];
    const int tid = threadIdx.x;
    const int bn = blockIdx.x * 128;
    const int bm = blockIdx.y * 128;
    const int lr = tid >> 2;
    const int lk = (tid & 3) << 2;
    int n1 = bn + lr, n2 = bn + lr + 64;
    if (permB) {
        int r1 = n1 % 96, r2 = n2 % 96;
        n1 = (r1 / 32) * 1024 + (n1 / 96) * 32 + (r1 % 32);
        n2 = (r2 / 32) * 1024 + (n2 / 96) * 32 + (r2 % 32);
    }
    const float* Ap  = A + (size_t)(bm + lr) * lda + lk;
    const float* Ap2 = A + (size_t)(bm + lr + 64) * lda + lk;
    const float* Bp  = B + (size_t)n1 * ldb + lk;
    const float* Bp2 = B + (size_t)n2 * ldb + lk;
    const int tx = tid & 15;
    const int ty = tid >> 4;
    float acc[8][8];
#pragma unroll
    for (int i = 0; i < 8; i++)
#pragma unroll
        for (int j = 0; j < 8; j++) acc[i][j] = 0.0f;
    float4 pa0 = *(const float4*)Ap;
    float4 pa1 = *(const float4*)Ap2;
    float4 pb0 = *(const float4*)Bp;
    float4 pb1 = *(const float4*)Bp2;
    const int ntiles = K >> 4;
    for (int tk = 0; tk < ntiles; ++tk) {
        As[(lk + 0) * 132 + lr] = pa0.x; As[(lk + 1) * 132 + lr] = pa0.y;
        As[(lk + 2) * 132 + lr] = pa0.z; As[(lk + 3) * 132 + lr] = pa0.w;
        As[(lk + 0) * 132 + lr + 64] = pa1.x; As[(lk + 1) * 132 + lr + 64] = pa1.y;
        As[(lk + 2) * 132 + lr + 64] = pa1.z; As[(lk + 3) * 132 + lr + 64] = pa1.w;
        Bs[(lk + 0) * 132 + lr] = pb0.x; Bs[(lk + 1) * 132 + lr] = pb0.y;
        Bs[(lk + 2) * 132 + lr] = pb0.z; Bs[(lk + 3) * 132 + lr] = pb0.w;
        Bs[(lk + 0) * 132 + lr + 64] = pb1.x; Bs[(lk + 1) * 132 + lr + 64] = pb1.y;
        Bs[(lk + 2) * 132 + lr + 64] = pb1.z; Bs[(lk + 3) * 132 + lr + 64] = pb1.w;
        __syncthreads();
        if (tk + 1 < ntiles) {
            pa0 = *(const float4*)(Ap  + (tk + 1) * 16);
            pa1 = *(const float4*)(Ap2 + (tk + 1) * 16);
            pb0 = *(const float4*)(Bp  + (tk + 1) * 16);
            pb1 = *(const float4*)(Bp2 + (tk + 1) * 16);
        }
#pragma unroll
        for (int k = 0; k < 16; ++k) {
            float4 a0 = *(const float4*)&As[k * 132 + ty * 8];
            float4 a1 = *(const float4*)&As[k * 132 + ty * 8 + 4];
            float4 b0 = *(const float4*)&Bs[k * 132 + tx * 8];
            float4 b1 = *(const float4*)&Bs[k * 132 + tx * 8 + 4];
            float av[8] = {a0.x, a0.y, a0.z, a0.w, a1.x, a1.y, a1.z, a1.w};
            float bv[8] = {b0.x, b0.y, b0.z, b0.w, b1.x, b1.y, b1.z, b1.w};
#pragma unroll
            for (int i = 0; i < 8; i++)
#pragma unroll
                for (int j = 0; j < 8; j++)
                    acc[i][j] += av[i] * bv[j];
        }
        __syncthreads();
    }
    float bb[8];
#pragma unroll
    for (int j = 0; j < 8; j++) bb[j] = bias ? bias[bn + tx * 8 + j] : 0.0f;
#pragma unroll
    for (int i = 0; i < 8; i++) {
        size_t off = (size_t)(bm + ty * 8 + i) * ldc + bn + tx * 8;
        float4 v0 = make_float4(acc[i][0] + bb[0], acc[i][1] + bb[1],
                                acc[i][2] + bb[2], acc[i][3] + bb[3]);
        float4 v1 = make_float4(acc[i][4] + bb[4], acc[i][5] + bb[5],
                                acc[i][6] + bb[6], acc[i][7] + bb[7]);
        *(float4*)(Cm + off) = v0;
        *(float4*)(Cm + off + 4) = v1;
        if (Cm2) { *(float4*)(Cm2 + off) = v0; *(float4*)(Cm2 + off + 4) = v1; }
    }
}

// one launch, grid (24,32,4): z=0 T0, z=1 Z0, z=2 OutZ, z=3 h1&h2
__global__ __launch_bounds__(256, 2)
void prep_gemms(const float* __restrict__ zin,
                const float* __restrict__ w_ih0,
                const float* __restrict__ z2h_w, const float* __restrict__ z2h_b,
                const float* __restrict__ h2o_w, const float* __restrict__ h2o_b)
{
    int zz = blockIdx.z;
    if (zz == 0) {
        if (blockIdx.y != 0 || blockIdx.x >= 24) return;
        sgemm_body(NH, g_Esw, NH, w_ih0, LDW, nullptr, g_T0, nullptr, NH3, 1);
    } else if (zz == 1) {
        if (blockIdx.x >= 24) return;
        sgemm_body(NLAT, zin, NLAT, w_ih0 + NH, LDW, g_bih0p, g_Z0, nullptr, NH3, 1);
    } else if (zz == 2) {
        if (blockIdx.x != 0) return;
        sgemm_body(NLAT, zin, NLAT, h2o_w + NH, LDW, h2o_b, g_OutZ, nullptr, NCHAR, 0);
    } else {
        if (blockIdx.x >= 8) return;
        sgemm_body(NLAT, zin, NLAT, z2h_w, NLAT, z2h_b, g_h1, g_h2, NH, 0);
    }
}

// ===================== splits ==============================================
__global__ void hsplit_kernel() {   // h1 == h2 initially; fill h1 buf0 + h2
    int i = blockIdx.x * blockDim.x + threadIdx.x;
    if (i < BATCH * NH) {
        float v = g_h1[i];
        __half h = __float2half_rn(v);
        __half lo = __float2half_rn(v - __half2float(h));
        g_h1hi[0][i] = h; g_h1lo[0][i] = lo;
        g_h2hi[i] = h;    g_h2lo[i] = lo;
    }
}
// grid (12288,1,4): z<3 permuted gate-weight splits, z=3 h2o_w plain split
__global__ void wsplit_kernel(const float* __restrict__ w_hh0,
                              const float* __restrict__ w_ih1,
                              const float* __restrict__ w_hh1,
                              const float* __restrict__ h2o_w)
{
    int zz = blockIdx.z;
    int i = blockIdx.x * blockDim.x + threadIdx.x;
    if (zz < 3) {
        if (i >= NH3 * NH) return;
        const float* src = (zz == 0) ? w_hh0 : (zz == 1) ? w_ih1 : w_hh1;
        __half* hi = (zz == 0) ? g_Whh0hi : (zz == 1) ? g_Wih1hi : g_Whh1hi;
        __half* lo = (zz == 0) ? g_Whh0lo : (zz == 1) ? g_Wih1lo : g_Whh1lo;
        int r = i >> 10, cc = i & 1023;
        int g = r >> 10, u = r & 1023;
        int dr = PERMC(g, u);
        float v = src[(size_t)r * NH + cc];
        __half h = __float2half_rn(v);
        hi[(size_t)dr * NH + cc] = h;
        lo[(size_t)dr * NH + cc] = __float2half_rn(v - __half2float(h));
    } else {
        if (i >= NCHAR * NH) return;
        int r = i >> 10, cc = i & 1023;
        float v = h2o_w[(size_t)r * LDW + cc];
        __half h = __float2half_rn(v);
        g_Wouthi[i] = h;
        g_Woutlo[i] = __float2half_rn(v - __half2float(h));
    }
}

// ===================== mma.sync fp16 split GEMM core ========================
#define SMOFF(r, c) ((r) * 128 + ((((c) ^ ((r) & 7)) << 4)))

__device__ __forceinline__ uint32_t smem_u32(const void* p) {
    uint32_t a;
    asm("{ .reg .u64 t; cvta.to.shared.u64 t, %1; cvt.u32.u64 %0, t; }"
        : "=r"(a) : "l"(p));
    return a;
}
__device__ __forceinline__ void cp16(uint32_t dst, const void* src) {
    asm volatile("cp.async.cg.shared.global [%0], [%1], 16;"
                 :: "r"(dst), "l"(src));
}
__device__ __forceinline__ void ldm_x4(uint32_t* r, uint32_t addr) {
    asm volatile("ldmatrix.sync.aligned.m8n8.x4.shared.b16 {%0,%1,%2,%3}, [%4];"
                 : "=r"(r[0]), "=r"(r[1]), "=r"(r[2]), "=r"(r[3]) : "r"(addr));
}
__device__ __forceinline__ void ldm_x2(uint32_t* r, uint32_t addr) {
    asm volatile("ldmatrix.sync.aligned.m8n8.x2.shared.b16 {%0,%1}, [%2];"
                 : "=r"(r[0]), "=r"(r[1]) : "r"(addr));
}
__device__ __forceinline__ void mma16816f(float* c, const uint32_t* a, const uint32_t* b) {
    asm volatile("mma.sync.aligned.m16n8k16.row.col.f32.f16.f16.f32 "
                 "{%0,%1,%2,%3}, {%4,%5,%6,%7}, {%8,%9}, {%0,%1,%2,%3};"
                 : "+f"(c[0]), "+f"(c[1]), "+f"(c[2]), "+f"(c[3])
                 : "r"(a[0]), "r"(a[1]), "r"(a[2]), "r"(a[3]), "r"(b[0]), "r"(b[1]));
}

template<int MT, int NB>
__device__ __forceinline__ void issue_stage(
    uint32_t sm_stage, const __half* Abase, const __half* Bbase,
    int bm, int bn, int colH, int tid)
{
    constexpr int TPR = 8 / MT;
    int r  = tid / TPR;
    int c0 = (tid % TPR) * MT;
    const __half* ag = Abase + (size_t)(bm + r) * NH + colH + c0 * 8;
#pragma unroll
    for (int j = 0; j < MT; ++j)
        cp16(sm_stage + SMOFF(r, c0 + j), ag + j * 8);
    uint32_t sB = sm_stage + MT * 4096;
    if (NB == 128 || tid < 2 * NB) {
        int r2 = tid >> 1, d0 = (tid & 1) * 4;
        const __half* bg = Bbase + (size_t)(bn + r2) * NH + colH + d0 * 8;
#pragma unroll
        for (int j = 0; j < 4; ++j)
            cp16(sB + SMOFF(r2, d0 + j), bg + j * 8);
    }
}

template<int MT, int NB, int NT>
__device__ __forceinline__ void mma_mainloop(
    const __half* __restrict__ Ahi, const __half* __restrict__ Alo,
    const __half* __restrict__ Bhi, const __half* __restrict__ Blo,
    int bm, int bn, char* smem, float (&acc)[MT][NT][4])
{
    constexpr int STB = MT * 4096 + NB * 128;
    const int tid = threadIdx.x;
    const int wid = tid >> 5, l = tid & 31;
    const int wm = wid >> 2, wn = wid & 3;
    uint32_t sbase = smem_u32(smem);

#pragma unroll
    for (int mt = 0; mt < MT; ++mt)
#pragma unroll
        for (int nt = 0; nt < NT; ++nt)
#pragma unroll
            for (int e = 0; e < 4; ++e) acc[mt][nt][e] = 0.0f;

    issue_stage<MT, NB>(sbase, Ahi, Bhi, bm, bn, 0, tid);
    asm volatile("cp.async.commit_group;");
    issue_stage<MT, NB>(sbase + STB, Ahi, Bhi, bm, bn, 64, tid);
    asm volatile("cp.async.commit_group;");

#pragma unroll 1
    for (int kc = 0; kc < KCH; ++kc) {
        asm volatile("cp.async.wait_group 1;");
        __syncthreads();
        int kn = kc + 2;
        if (kn < KCH) {
            const __half* Ab = (kn < 32) ? Ahi : Alo;
            const __half* Bb = (kn >= 16 && kn < 32) ? Blo : Bhi;
            issue_stage<MT, NB>(sbase + (kn % 3) * STB, Ab, Bb, bm, bn,
                                (kn & 15) << 6, tid);
        }
        asm volatile("cp.async.commit_group;");

        uint32_t sA = sbase + (kc % 3) * STB;
        uint32_t sB = sA + MT * 4096;
#pragma unroll
        for (int kt = 0; kt < 4; ++kt) {
            uint32_t af[MT][4];
#pragma unroll
            for (int mt = 0; mt < MT; ++mt) {
                int row = wm * (MT * 16) + mt * 16 + (l & 15);
                ldm_x4(af[mt], sA + SMOFF(row, kt * 2 + (l >> 4)));
            }
            uint32_t bfr[NT][2];
            if (NT == 4) {
#pragma unroll
                for (int ntp = 0; ntp < 2; ++ntp) {
                    int g = l >> 3;
                    int nrow = wn * 32 + ntp * 16 + ((g >> 1) << 3) + (l & 7);
                    uint32_t rr[4];
                    ldm_x4(rr, sB + SMOFF(nrow, kt * 2 + (g & 1)));
                    bfr[2 * ntp][0] = rr[0]; bfr[2 * ntp][1] = rr[1];
                    bfr[2 * ntp + 1][0] = rr[2]; bfr[2 * ntp + 1][1] = rr[3];
                }
            } else {
#pragma unroll
                for (int nt = 0; nt < NT; ++nt) {
                    int n0 = wn * (NT * 8) + nt * 8;
                    ldm_x2(bfr[nt], sB + SMOFF(n0 + (l & 7), kt * 2 + ((l >> 3) & 1)));
                }
            }
#pragma unroll
            for (int mt = 0; mt < MT; ++mt)
#pragma unroll
                for (int nt = 0; nt < NT; ++nt)
                    mma16816f(acc[mt][nt], af[mt], bfr[nt]);
        }
    }
    asm volatile("cp.async.wait_group 0;");
}

// ===================== combined gh kernel: grid (32,32,2) ===================
// z=0: gh0 MMA (A=h1 old parity) + fused gates1 -> h1 (new parity)
// z=1: gh1 MMA (A=h2) -> bufB (+bhh1p)
__global__ __launch_bounds__(256, 2)
void gh_kernel(const __half* __restrict__ h1hiA, const __half* __restrict__ h1loA,
               const __half* __restrict__ Whh0hi, const __half* __restrict__ Whh0lo,
               const __half* __restrict__ h2hi, const __half* __restrict__ h2lo,
               const __half* __restrict__ Whh1hi, const __half* __restrict__ Whh1lo,
               float* __restrict__ h1O, __half* __restrict__ h1hiB, __half* __restrict__ h1loB)
{
    extern __shared__ char smem[];
    const int zz = blockIdx.z;
    const int bn = blockIdx.x * 96, bm = blockIdx.y * 128;
    const int tid = threadIdx.x;
    const int wid = tid >> 5, l = tid & 31;
    const int wm = wid >> 2, wn = wid & 3;

    const __half* Ahi = zz ? h2hi : h1hiA;
    const __half* Alo = zz ? h2lo : h1loA;
    const __half* Bhi = zz ? Whh1hi : Whh0hi;
    const __half* Blo = zz ? Whh1lo : Whh0lo;

    float acc[4][3][4];
    mma_mainloop<4, 96, 3>(Ahi, Alo, Bhi, Blo, bm, bn, smem, acc);

    if (zz == 1) {   // plain: bufB = acc + bhh1p
#pragma unroll
        for (int mt = 0; mt < 4; ++mt)
#pragma unroll
            for (int nt = 0; nt < 3; ++nt) {
                int row = bm + wm * 64 + mt * 16 + (l >> 2);
                int col = bn + wn * 24 + nt * 8 + ((l & 3) << 1);
                float b0 = g_bhh1p[col], b1 = g_bhh1p[col + 1];
                *(float2*)&g_bufB[(size_t)row * NH3 + col] =
                    make_float2(acc[mt][nt][0] + b0, acc[mt][nt][1] + b1);
                *(float2*)&g_bufB[(size_t)(row + 8) * NH3 + col] =
                    make_float2(acc[mt][nt][2] + b0, acc[mt][nt][3] + b1);
            }
        return;
    }

    // z=0: gates1 epilogue
    __syncthreads();
    float* Cs = (float*)smem;
#pragma unroll
    for (int mt = 0; mt < 4; ++mt)
#pragma unroll
        for (int nt = 0; nt < 3; ++nt) {
            int r0 = wm * 64 + mt * 16 + (l >> 2);
            int c0 = wn * 24 + nt * 8 + ((l & 3) << 1);
            Cs[r0 * 100 + c0]           = acc[mt][nt][0];
            Cs[r0 * 100 + c0 + 1]       = acc[mt][nt][1];
            Cs[(r0 + 8) * 100 + c0]     = acc[mt][nt][2];
            Cs[(r0 + 8) * 100 + c0 + 1] = acc[mt][nt][3];
        }
    __syncthreads();

    const int ul = l;
    const int u  = bn / 3 + ul;
    float bh0 = g_bhh0p[bn + ul];
    float bh1 = g_bhh0p[bn + 32 + ul];
    float bh2 = g_bhh0p[bn + 64 + ul];
#pragma unroll 2
    for (int i = 0; i < 16; ++i) {
        int rb = wid * 16 + i;
        int b = bm + rb;
        float ghr = Cs[rb * 100 + ul] + bh0;
        float ghz = Cs[rb * 100 + 32 + ul] + bh1;
        float ghn = Cs[rb * 100 + 64 + ul] + bh2;
        const float* gp = g_Z0 + (size_t)b * NH3 + bn;
        int cb = g_c[b];
        const float* tp = g_T0 + (size_t)cb * NH3 + bn;
        float gir = gp[ul] + tp[ul];
        float giz = gp[32 + ul] + tp[32 + ul];
        float gin = gp[64 + ul] + tp[64 + ul];
        float r  = 1.0f / (1.0f + expf(-(gir + ghr)));
        float zg = 1.0f / (1.0f + expf(-(giz + ghz)));
        float nn = tanhf(gin + r * ghn);
        size_t hidx = (size_t)b * NH + u;
        float hv = h1O[hidx];
        float hn2 = (1.0f - zg) * nn + zg * hv;
        h1O[hidx] = hn2;
        __half hb = __float2half_rn(hn2);
        h1hiB[hidx] = hb;
        h1loB[hidx] = __float2half_rn(hn2 - __half2float(hb));
    }
}

// ===================== gi kernel: gi1 MMA + fused gates2 ====================
// A = h1 (new), gh side from bufB; writes h2 + splits (A != output -> no race)
__global__ __launch_bounds__(256, 2)
void gi_kernel(const __half* __restrict__ h1hi, const __half* __restrict__ h1lo)
{
    extern __shared__ char smem[];
    const int bn = blockIdx.x * 96, bm = blockIdx.y * 128;
    const int tid = threadIdx.x;
    const int wid = tid >> 5, l = tid & 31;
    const int wm = wid >> 2, wn = wid & 3;
    float acc[4][3][4];
    mma_mainloop<4, 96, 3>(h1hi, h1lo, g_Wih1hi, g_Wih1lo, bm, bn, smem, acc);

    __syncthreads();
    float* Cs = (float*)smem;
#pragma unroll
    for (int mt = 0; mt < 4; ++mt)
#pragma unroll
        for (int nt = 0; nt < 3; ++nt) {
            int r0 = wm * 64 + mt * 16 + (l >> 2);
            int c0 = wn * 24 + nt * 8 + ((l & 3) << 1);
            Cs[r0 * 100 + c0]           = acc[mt][nt][0];
            Cs[r0 * 100 + c0 + 1]       = acc[mt][nt][1];
            Cs[(r0 + 8) * 100 + c0]     = acc[mt][nt][2];
            Cs[(r0 + 8) * 100 + c0 + 1] = acc[mt][nt][3];
        }
    __syncthreads();

    const int ul = l;
    const int u  = bn / 3 + ul;
    float bi0 = g_bih1p[bn + ul];
    float bi1 = g_bih1p[bn + 32 + ul];
    float bi2 = g_bih1p[bn + 64 + ul];
#pragma unroll 2
    for (int i = 0; i < 16; ++i) {
        int rb = wid * 16 + i;
        int b = bm + rb;
        float gir = Cs[rb * 100 + ul] + bi0;
        float giz = Cs[rb * 100 + 32 + ul] + bi1;
        float gin = Cs[rb * 100 + 64 + ul] + bi2;
        const float* gp = g_bufB + (size_t)b * NH3 + bn;
        float ghr = gp[ul], ghz = gp[32 + ul], ghn = gp[64 + ul];
        float r  = 1.0f / (1.0f + expf(-(gir + ghr)));
        float zg = 1.0f / (1.0f + expf(-(giz + ghz)));
        float nn = tanhf(gin + r * ghn);
        size_t hidx = (size_t)b * NH + u;
        float hv = g_h2[hidx];
        float hn2 = (1.0f - zg) * nn + zg * hv;
        g_h2[hidx] = hn2;
        __half hb = __float2half_rn(hn2);
        g_h2hi[hidx] = hb;
        g_h2lo[hidx] = __float2half_rn(hn2 - __half2float(hb));
    }
}

// ===================== h2o: BM=32, fused argmax =============================
__global__ __launch_bounds__(256)
void h2o_mma_kernel(float* __restrict__ out, int t)
{
    extern __shared__ char smem[];
    const int bm = blockIdx.x * 32;
    const int tid = threadIdx.x;
    const int wid = tid >> 5, l = tid & 31;
    const int wm = wid >> 2, wn = wid & 3;
    float acc[1][4][4];
    mma_mainloop<1, 128, 4>(g_h2hi, g_h2lo, g_Wouthi, g_Woutlo, bm, 0, smem, acc);
    __syncthreads();

    float* lg = (float*)smem;
#pragma unroll
    for (int nt = 0; nt < 4; ++nt) {
        int rl = wm * 16 + (l >> 2);
        int cl = wn * 32 + nt * 8 + ((l & 3) << 1);
        lg[rl * 132 + cl]           = acc[0][nt][0];
        lg[rl * 132 + cl + 1]       = acc[0][nt][1];
        lg[(rl + 8) * 132 + cl]     = acc[0][nt][2];
        lg[(rl + 8) * 132 + cl + 1] = acc[0][nt][3];
    }
    __syncthreads();

    if (tid < 32) {
        int row = bm + tid;
        const float* oz = g_OutZ + (size_t)row * NCHAR;
        float* op = out + (size_t)row * (NSTEP * NCHAR) + t * NCHAR;
        float best = -FLT_MAX;
        int bi = 0;
#pragma unroll 4
        for (int c = 0; c < NCHAR; ++c) {
            float v = lg[tid * 132 + c] + oz[c];
            op[c] = v;
            if (v > best) { best = v; bi = c; }
        }
        g_c[row] = bi;
    }
}

// ===================== launch ===============================================
extern "C" void kernel_launch(void* const* d_in, const int* in_sizes, int n_in,
                              void* d_out, int out_size)
{
    const float* z       = (const float*)d_in[0];
    const float* embed_w = (const float*)d_in[1];
    const float* z2h_w   = (const float*)d_in[2];
    const float* z2h_b   = (const float*)d_in[3];
    const float* w_ih0   = (const float*)d_in[4];
    const float* w_hh0   = (const float*)d_in[5];
    const float* b_ih0   = (const float*)d_in[6];
    const float* b_hh0   = (const float*)d_in[7];
    const float* w_ih1   = (const float*)d_in[8];
    const float* w_hh1   = (const float*)d_in[9];
    const float* b_ih1   = (const float*)d_in[10];
    const float* b_hh1   = (const float*)d_in[11];
    const float* h2o_w   = (const float*)d_in[12];
    const float* h2o_b   = (const float*)d_in[13];
    float* out = (float*)d_out;

    __half *h1hi0, *h1lo0, *h1hi1, *h1lo1;
    cudaGetSymbolAddress((void**)&h1hi0, g_h1hi);   // [0]
    cudaGetSymbolAddress((void**)&h1lo0, g_h1lo);
    h1hi1 = h1hi0 + (size_t)BATCH * NH;
    h1lo1 = h1lo0 + (size_t)BATCH * NH;

    const int smem_big = 3 * (4 * 4096 + 96 * 128);   // 86016
    const int smem_h2o = 3 * (1 * 4096 + 128 * 128);  // 61440
    cudaFuncSetAttribute(gh_kernel, cudaFuncAttributeMaxDynamicSharedMemorySize, smem_big);
    cudaFuncSetAttribute(gi_kernel, cudaFuncAttributeMaxDynamicSharedMemorySize, smem_big);
    cudaFuncSetAttribute(h2o_mma_kernel, cudaFuncAttributeMaxDynamicSharedMemorySize, smem_h2o);

    // ---- precompute: 4 launches (so -s 5 lands on a step GEMM) ----
    prep0_kernel<<<(NCHAR * NH + 255) / 256, 256>>>(embed_w, b_ih0, b_hh0, b_ih1, b_hh1);
    prep_gemms<<<dim3(24, 32, 4), 256>>>(z, w_ih0, z2h_w, z2h_b, h2o_w, h2o_b);
    hsplit_kernel<<<BATCH * NH / 256, 256>>>();
    wsplit_kernel<<<dim3(NH3 * NH / 256, 1, 4), 256>>>(w_hh0, w_ih1, w_hh1, h2o_w);

    // ---- 64 steps, 3 launches each; h1 fp16 splits ping-pong (race fix) ----
    for (int t = 0; t < NSTEP; ++t) {
        int p = t & 1;
        __half* rhi = p ? h1hi1 : h1hi0;
        __half* rlo = p ? h1lo1 : h1lo0;
        __half* whi = p ? h1hi0 : h1hi1;
        __half* wlo = p ? h1lo0 : h1lo1;

        float* h1p;
        cudaGetSymbolAddress((void**)&h1p, g_h1);
        __half *h2hip, *h2lop, *Whh0hip, *Whh0lop, *Whh1hip, *Whh1lop;
        cudaGetSymbolAddress((void**)&h2hip, g_h2hi);
        cudaGetSymbolAddress((void**)&h2lop, g_h2lo);
        cudaGetSymbolAddress((void**)&Whh0hip, g_Whh0hi);
        cudaGetSymbolAddress((void**)&Whh0lop, g_Whh0lo);
        cudaGetSymbolAddress((void**)&Whh1hip, g_Whh1hi);
        cudaGetSymbolAddress((void**)&Whh1lop, g_Whh1lo);

        gh_kernel<<<dim3(32, 32, 2), 256, smem_big>>>(
            rhi, rlo, Whh0hip, Whh0lop, h2hip, h2lop, Whh1hip, Whh1lop,
            h1p, whi, wlo);
        gi_kernel<<<dim3(32, 32), 256, smem_big>>>(whi, wlo);
        h2o_mma_kernel<<<BATCH / 32, 256, smem_h2o>>>(out, t);
    }
}